// round 6
// baseline (speedup 1.0000x reference)
#include <cuda_runtime.h>
#include <math.h>

#define NPT 3000
#define BB 2
#define CCH 128
#define CH 64
#define LL 6
#define EPSBN 1e-5f
#define ATT_SCALE 0.08838834764831845f  // 1/sqrt(128)
#define MSPLIT 4
#define MCHUNK 752

typedef unsigned long long ull;

__device__ __forceinline__ void ffma2(ull &d, ull a, ull b) {
    asm("fma.rn.f32x2 %0, %1, %2, %0;" : "+l"(d) : "l"(a), "l"(b));
}
__device__ __forceinline__ float2 unp(ull v) {
    unsigned lo, hi;
    asm("mov.b64 {%0,%1}, %2;" : "=r"(lo), "=r"(hi) : "l"(v));
    return make_float2(__uint_as_float(lo), __uint_as_float(hi));
}
__device__ __forceinline__ ull d2u(double d) { return __double_as_longlong(d); }
__device__ __forceinline__ float sqrt_approx(float x) {
    float r; asm("sqrt.approx.f32 %0, %1;" : "=f"(r) : "f"(x)); return r;
}

// ---------------- device scratch ----------------
__device__ float g_x[BB*CCH*NPT];
__device__ float g_y[BB*CCH*NPT];
__device__ float g_q[BB*CCH*NPT];
__device__ float g_k[BB*CCH*NPT];
__device__ float g_v[BB*CCH*NPT];
__device__ float g_h[BB*CCH*NPT];
__device__ float g_Mp[(size_t)MSPLIT*BB*CCH*NPT];
__device__ float g_P[(size_t)BB*NPT*NPT];
__device__ float g_SC[(size_t)BB*NPT*NPT];
__device__ float g_scl[CCH],  g_shf[CCH];
__device__ float g_scl1[CCH], g_shf1[CCH];
__device__ float g_scl2[CCH], g_shf2[CCH];

// ---------------- init embedding ----------------
__global__ void init_conv_kernel(const float* __restrict__ corr, const float* __restrict__ W,
                                 const float* __restrict__ bias, float* __restrict__ X)
{
    __shared__ float Ws[CCH*6];
    __shared__ float bs[CCH];
    int tid = threadIdx.x;
    for (int i = tid; i < CCH*6; i += blockDim.x) Ws[i] = W[i];
    for (int i = tid; i < CCH;   i += blockDim.x) bs[i] = bias[i];
    __syncthreads();
    int idx = blockIdx.x * blockDim.x + tid;
    if (idx >= BB*NPT) return;
    int b = idx / NPT, n = idx - b*NPT;
    float cp[6];
#pragma unroll
    for (int j = 0; j < 6; j++) cp[j] = corr[(size_t)idx*6 + j];
    for (int co = 0; co < CCH; co++) {
        float a = bs[co];
#pragma unroll
        for (int j = 0; j < 6; j++) a += Ws[co*6 + j] * cp[j];
        X[((size_t)b*CCH + co)*NPT + n] = a;
    }
}

// ---------------- SC precompute: SC[b,o,i] = max(0,1-(ds-dt)^2) * ATT_SCALE ----------------
__global__ void __launch_bounds__(256) sc_kernel(const float* __restrict__ src,
                                                 const float* __restrict__ tgt,
                                                 float* __restrict__ SC)
{
    __shared__ float pO[128][6];
    __shared__ float pI[128][6];
    int tid = threadIdx.x;
    int b = blockIdx.z;
    int o0 = blockIdx.y << 7, i0 = blockIdx.x << 7;
    {
        int r = tid & 127;
        int n = (tid < 128 ? o0 : i0) + r;
        float* dst = (tid < 128) ? pO[r] : pI[r];
        if (n < NPT) {
#pragma unroll
            for (int j = 0; j < 3; j++) {
                dst[j]     = src[((size_t)b*NPT + n)*3 + j];
                dst[3 + j] = tgt[((size_t)b*NPT + n)*3 + j];
            }
        } else {
#pragma unroll
            for (int j = 0; j < 6; j++) dst[j] = 0.f;
        }
    }
    __syncthreads();
    int ty = tid >> 4, tx = tid & 15;
    int ob = ty << 3, ib = tx << 3;
    int icol = i0 + ib;
    if (icol >= NPT) return;
#pragma unroll
    for (int mi = 0; mi < 8; mi++) {
        int o = o0 + ob + mi;
        if (o >= NPT) continue;
        float out[8];
#pragma unroll
        for (int ni = 0; ni < 8; ni++) {
            float dx = pO[ob+mi][0] - pI[ib+ni][0];
            float dy = pO[ob+mi][1] - pI[ib+ni][1];
            float dz = pO[ob+mi][2] - pI[ib+ni][2];
            float ds = sqrt_approx(dx*dx + dy*dy + dz*dz);
            dx = pO[ob+mi][3] - pI[ib+ni][3];
            dy = pO[ob+mi][4] - pI[ib+ni][4];
            dz = pO[ob+mi][5] - pI[ib+ni][5];
            float dt = sqrt_approx(dx*dx + dy*dy + dz*dz);
            float d = ds - dt;
            out[ni] = fmaxf(1.f - d*d, 0.f) * ATT_SCALE;
        }
        size_t off = ((size_t)b*NPT + o)*NPT + icol;
        *(float4*)&SC[off]     = make_float4(out[0], out[1], out[2], out[3]);
        *(float4*)&SC[off + 4] = make_float4(out[4], out[5], out[6], out[7]);
    }
}

// ---------------- scores: P[b,o,i] = SC[b,o,i] * sum_c Q[c,o]K[c,i] ----------------
// 128x128 tile, 256 threads, 8x8/thread, f32x2 packed along i, Q duplicated in smem.
__global__ void __launch_bounds__(256) gemm_scores_kernel(const float* __restrict__ Q,
                                                          const float* __restrict__ K,
                                                          const float* __restrict__ SC,
                                                          float* __restrict__ P)
{
    __shared__ float Qs[16][256];   // o duplicated: Qs[kk][2o],[2o+1]
    __shared__ float Ks[16][128];
    int tid = threadIdx.x;
    int b = blockIdx.z, o0 = blockIdx.y << 7, i0 = blockIdx.x << 7;
    int ty = tid >> 4, tx = tid & 15;
    ull acc[8][4];
#pragma unroll
    for (int i = 0; i < 8; i++)
#pragma unroll
        for (int j = 0; j < 4; j++) acc[i][j] = 0ull;

#pragma unroll 1
    for (int kt = 0; kt < CCH; kt += 16) {
        __syncthreads();
#pragma unroll
        for (int t = 0; t < 2; t++) {
            int idx = tid + (t << 8);
            int kk = idx >> 5, j4 = (idx & 31) << 2;
            float4 qv = make_float4(0.f,0.f,0.f,0.f);
            float4 kv = make_float4(0.f,0.f,0.f,0.f);
            if (o0 + j4 < NPT) qv = *(const float4*)&Q[((size_t)(b*CCH + kt + kk))*NPT + o0 + j4];
            if (i0 + j4 < NPT) kv = *(const float4*)&K[((size_t)(b*CCH + kt + kk))*NPT + i0 + j4];
            *(float4*)&Qs[kk][2*j4]     = make_float4(qv.x, qv.x, qv.y, qv.y);
            *(float4*)&Qs[kk][2*j4 + 4] = make_float4(qv.z, qv.z, qv.w, qv.w);
            *(float4*)&Ks[kk][j4] = kv;
        }
        __syncthreads();
#pragma unroll
        for (int kk = 0; kk < 16; kk++) {
            const double2* qp = (const double2*)&Qs[kk][ty << 4];
            const double2* kp = (const double2*)&Ks[kk][tx << 3];
            double2 q0 = qp[0], q1 = qp[1], q2 = qp[2], q3 = qp[3];
            double2 k0 = kp[0], k1 = kp[1];
            ull a[8]   = {d2u(q0.x), d2u(q0.y), d2u(q1.x), d2u(q1.y),
                          d2u(q2.x), d2u(q2.y), d2u(q3.x), d2u(q3.y)};
            ull bb4[4] = {d2u(k0.x), d2u(k0.y), d2u(k1.x), d2u(k1.y)};
#pragma unroll
            for (int mi = 0; mi < 8; mi++)
#pragma unroll
                for (int ni = 0; ni < 4; ni++)
                    ffma2(acc[mi][ni], a[mi], bb4[ni]);
        }
    }

    int icol = i0 + (tx << 3);
    if (icol >= NPT) return;
    int orow = o0 + (ty << 3);
#pragma unroll
    for (int mi = 0; mi < 8; mi++) {
        int o = orow + mi;
        if (o >= NPT) continue;
        size_t off = ((size_t)b*NPT + o)*NPT + icol;
        float4 s0 = *(const float4*)&SC[off];
        float4 s1 = *(const float4*)&SC[off + 4];
        float2 f0 = unp(acc[mi][0]), f1 = unp(acc[mi][1]);
        float2 f2 = unp(acc[mi][2]), f3 = unp(acc[mi][3]);
        *(float4*)&P[off]     = make_float4(f0.x*s0.x, f0.y*s0.y, f1.x*s0.z, f1.y*s0.w);
        *(float4*)&P[off + 4] = make_float4(f2.x*s1.x, f2.y*s1.y, f3.x*s1.z, f3.y*s1.w);
    }
}

// ---------------- row softmax in-place ----------------
__global__ void softmax_kernel(float* __restrict__ P)
{
    __shared__ float row[NPT];
    __shared__ float red[9];
    int o = blockIdx.x, b = blockIdx.y;
    int tid = threadIdx.x;
    float* base = P + ((size_t)b*NPT + o)*NPT;

    float mx = -3.4e38f;
    for (int i = tid*4; i < NPT; i += 1024) {
        float4 v = *(const float4*)&base[i];
        *(float4*)&row[i] = v;
        mx = fmaxf(mx, fmaxf(fmaxf(v.x, v.y), fmaxf(v.z, v.w)));
    }
#pragma unroll
    for (int s = 16; s; s >>= 1) mx = fmaxf(mx, __shfl_xor_sync(0xffffffffu, mx, s));
    int wid = tid >> 5, lane = tid & 31;
    if (lane == 0) red[wid] = mx;
    __syncthreads();
    if (tid == 0) {
        float m = red[0];
        for (int w = 1; w < 8; w++) m = fmaxf(m, red[w]);
        red[8] = m;
    }
    __syncthreads();
    mx = red[8];

    float sum = 0.f;
    for (int i = tid*4; i < NPT; i += 1024) {
        float4 v = *(float4*)&row[i];
        v.x = __expf(v.x - mx); v.y = __expf(v.y - mx);
        v.z = __expf(v.z - mx); v.w = __expf(v.w - mx);
        *(float4*)&row[i] = v;
        sum += v.x + v.y + v.z + v.w;
    }
#pragma unroll
    for (int s = 16; s; s >>= 1) sum += __shfl_xor_sync(0xffffffffu, sum, s);
    __syncthreads();
    if (lane == 0) red[wid] = sum;
    __syncthreads();
    if (tid == 0) {
        float s = 0.f;
        for (int w = 0; w < 8; w++) s += red[w];
        red[8] = s;
    }
    __syncthreads();
    float inv = 1.f / red[8];

    for (int i = tid*4; i < NPT; i += 1024) {
        float4 v = *(float4*)&row[i];
        v.x *= inv; v.y *= inv; v.z *= inv; v.w *= inv;
        *(float4*)&base[i] = v;
    }
}

// ---------------- msg (NT, split-K): Mp[s][b,c,o] = sum_{i in split s} V[b,c,i] P[b,o,i] ----
// 128c x 128o tile, 256 threads, 8x8/thread, f32x2 packed along c, P duplicated in smem.
__global__ void __launch_bounds__(256) gemm_msg_kernel(const float* __restrict__ V,
                                                       const float* __restrict__ P,
                                                       float* __restrict__ Mp)
{
    __shared__ float Vs[16][128];
    __shared__ float Ps[16][256];   // o duplicated
    int tid = threadIdx.x;
    int b = blockIdx.z, s = blockIdx.y, o0 = blockIdx.x << 7;
    int ty = tid >> 4, tx = tid & 15;
    int ib0 = s * MCHUNK;
    int ilim = min(ib0 + MCHUNK, NPT);
    ull acc[4][8];
#pragma unroll
    for (int i = 0; i < 4; i++)
#pragma unroll
        for (int j = 0; j < 8; j++) acc[i][j] = 0ull;

#pragma unroll 1
    for (int ib = ib0; ib < ib0 + MCHUNK; ib += 16) {
        __syncthreads();
#pragma unroll
        for (int t = 0; t < 2; t++) {
            int idx = tid + (t << 8);
            int r = idx >> 2;              // 0..127
            int kk4 = (idx & 3) << 2;
            int ii = ib + kk4;
            float4 v = make_float4(0.f,0.f,0.f,0.f);
            if (ii < ilim) v = *(const float4*)&V[((size_t)(b*CCH + r))*NPT + ii];
            Vs[kk4][r] = v.x; Vs[kk4+1][r] = v.y; Vs[kk4+2][r] = v.z; Vs[kk4+3][r] = v.w;
            float4 p = make_float4(0.f,0.f,0.f,0.f);
            int oo = o0 + r;
            if (ii < ilim && oo < NPT) p = *(const float4*)&P[((size_t)b*NPT + oo)*NPT + ii];
            Ps[kk4][2*r]   = p.x; Ps[kk4][2*r+1]   = p.x;
            Ps[kk4+1][2*r] = p.y; Ps[kk4+1][2*r+1] = p.y;
            Ps[kk4+2][2*r] = p.z; Ps[kk4+2][2*r+1] = p.z;
            Ps[kk4+3][2*r] = p.w; Ps[kk4+3][2*r+1] = p.w;
        }
        __syncthreads();
#pragma unroll
        for (int kk = 0; kk < 16; kk++) {
            const double2* vp = (const double2*)&Vs[kk][ty << 3];
            const double2* pp = (const double2*)&Ps[kk][tx << 4];
            double2 v0 = vp[0], v1 = vp[1];
            double2 p0 = pp[0], p1 = pp[1], p2 = pp[2], p3 = pp[3];
            ull a[4]  = {d2u(v0.x), d2u(v0.y), d2u(v1.x), d2u(v1.y)};
            ull bd[8] = {d2u(p0.x), d2u(p0.y), d2u(p1.x), d2u(p1.y),
                         d2u(p2.x), d2u(p2.y), d2u(p3.x), d2u(p3.y)};
#pragma unroll
            for (int cp = 0; cp < 4; cp++)
#pragma unroll
                for (int oi = 0; oi < 8; oi++)
                    ffma2(acc[cp][oi], a[cp], bd[oi]);
        }
    }

    int oc = o0 + (tx << 3);
    if (oc >= NPT) return;
    float* base = Mp + ((size_t)(s*BB + b))*CCH*NPT;
#pragma unroll
    for (int cp = 0; cp < 4; cp++) {
        int c = (ty << 3) + (cp << 1);
        float lo[8], hi[8];
#pragma unroll
        for (int oi = 0; oi < 8; oi++) { float2 f = unp(acc[cp][oi]); lo[oi] = f.x; hi[oi] = f.y; }
        *(float4*)&base[(size_t)c*NPT + oc]       = make_float4(lo[0], lo[1], lo[2], lo[3]);
        *(float4*)&base[(size_t)c*NPT + oc + 4]   = make_float4(lo[4], lo[5], lo[6], lo[7]);
        *(float4*)&base[(size_t)(c+1)*NPT + oc]     = make_float4(hi[0], hi[1], hi[2], hi[3]);
        *(float4*)&base[(size_t)(c+1)*NPT + oc + 4] = make_float4(hi[4], hi[5], hi[6], hi[7]);
    }
}

// ---------------- pointwise conv with fused input transforms ----------------
// INMODE: 0 = plain, 1 = relu(scl*x+shf) on input, 2 = sum of MSPLIT partial buffers
template<int INMODE, bool RELU, bool RESID>
__global__ void __launch_bounds__(256) conv_kernel(const float* __restrict__ X,
        const float* __restrict__ W, const float* __restrict__ bias,
        const float* __restrict__ scl, const float* __restrict__ shf,
        const float* __restrict__ R, float* __restrict__ Y, int Cin, int Cout)
{
    __shared__ float Ws[16][128];   // co duplicated
    __shared__ float Xs[16][64];
    __shared__ float sA[CCH], sB[CCH];
    int tid = threadIdx.x;
    int b = blockIdx.z, c0 = blockIdx.y << 6, n0 = blockIdx.x << 6;
    if (INMODE == 1) {
        if (tid < Cin) { sA[tid] = scl[tid]; sB[tid] = shf[tid]; }
    }
    int ty = tid >> 4, tx = tid & 15;
    ull acc[4][2];
#pragma unroll
    for (int i = 0; i < 4; i++) { acc[i][0] = 0ull; acc[i][1] = 0ull; }

#pragma unroll 1
    for (int kt = 0; kt < Cin; kt += 16) {
        __syncthreads();
        {
            int m = tid >> 2, kk4 = (tid & 3) << 2;
            float4 w = make_float4(0.f,0.f,0.f,0.f);
            if (c0 + m < Cout) w = *(const float4*)&W[(size_t)(c0 + m)*Cin + kt + kk4];
            Ws[kk4][2*m] = w.x;   Ws[kk4][2*m+1] = w.x;
            Ws[kk4+1][2*m] = w.y; Ws[kk4+1][2*m+1] = w.y;
            Ws[kk4+2][2*m] = w.z; Ws[kk4+2][2*m+1] = w.z;
            Ws[kk4+3][2*m] = w.w; Ws[kk4+3][2*m+1] = w.w;
        }
        {
            int kk = tid >> 4, j4 = (tid & 15) << 2;
            int ci = kt + kk;
            float4 v = make_float4(0.f,0.f,0.f,0.f);
            if (n0 + j4 < NPT) {
                size_t off = ((size_t)(b*Cin + ci))*NPT + n0 + j4;
                if (INMODE == 2) {
                    const size_t str = (size_t)BB*CCH*NPT;
                    float4 a0 = *(const float4*)&X[off];
                    float4 a1 = *(const float4*)&X[off + str];
                    float4 a2 = *(const float4*)&X[off + 2*str];
                    float4 a3 = *(const float4*)&X[off + 3*str];
                    v = make_float4(a0.x+a1.x+a2.x+a3.x, a0.y+a1.y+a2.y+a3.y,
                                    a0.z+a1.z+a2.z+a3.z, a0.w+a1.w+a2.w+a3.w);
                } else {
                    v = *(const float4*)&X[off];
                }
                if (INMODE == 1) {
                    float sa = sA[ci], sb = sB[ci];
                    v.x = fmaxf(fmaf(sa, v.x, sb), 0.f);
                    v.y = fmaxf(fmaf(sa, v.y, sb), 0.f);
                    v.z = fmaxf(fmaf(sa, v.z, sb), 0.f);
                    v.w = fmaxf(fmaf(sa, v.w, sb), 0.f);
                }
            }
            *(float4*)&Xs[kk][j4] = v;
        }
        __syncthreads();
#pragma unroll
        for (int kk = 0; kk < 16; kk++) {
            const double2* wp = (const double2*)&Ws[kk][ty << 3];
            double2 w0 = wp[0], w1 = wp[1];
            ull a[4] = {d2u(w0.x), d2u(w0.y), d2u(w1.x), d2u(w1.y)};
            const double2* xp = (const double2*)&Xs[kk][tx << 2];
            double2 x0 = xp[0];
            ull b0 = d2u(x0.x), b1 = d2u(x0.y);
#pragma unroll
            for (int mi = 0; mi < 4; mi++) {
                ffma2(acc[mi][0], a[mi], b0);
                ffma2(acc[mi][1], a[mi], b1);
            }
        }
    }

    int n = n0 + (tx << 2);
    if (n >= NPT) return;
#pragma unroll
    for (int mi = 0; mi < 4; mi++) {
        int co = c0 + (ty << 2) + mi;
        if (co >= Cout) continue;
        float bv = bias[co];
        float2 f0 = unp(acc[mi][0]), f1 = unp(acc[mi][1]);
        float4 o4 = make_float4(f0.x + bv, f0.y + bv, f1.x + bv, f1.y + bv);
        size_t off = ((size_t)(b*Cout + co))*NPT + n;
        if (RESID) {
            float4 r = *(const float4*)&R[off];
            o4.x += r.x; o4.y += r.y; o4.z += r.z; o4.w += r.w;
        }
        if (RELU) {
            o4.x = fmaxf(o4.x, 0.f); o4.y = fmaxf(o4.y, 0.f);
            o4.z = fmaxf(o4.z, 0.f); o4.w = fmaxf(o4.w, 0.f);
        }
        *(float4*)&Y[off] = o4;
    }
}

// ---------------- BN stats -> per-channel affine ----------------
__global__ void bn_stats_kernel(const float* __restrict__ Y, const float* __restrict__ g,
                                const float* __restrict__ beta, float* __restrict__ scl,
                                float* __restrict__ shf, int Cc)
{
    __shared__ float s1[256], s2[256];
    int c = blockIdx.x, tid = threadIdx.x;
    float a = 0.f, q = 0.f;
    for (int bb = 0; bb < BB; bb++) {
        const float* row = Y + ((size_t)(bb*Cc + c))*NPT;
        for (int i = tid*4; i < NPT; i += 1024) {
            float4 v = *(const float4*)&row[i];
            a += v.x + v.y + v.z + v.w;
            q += v.x*v.x + v.y*v.y + v.z*v.z + v.w*v.w;
        }
    }
    s1[tid] = a; s2[tid] = q;
    __syncthreads();
    for (int o = 128; o > 0; o >>= 1) {
        if (tid < o) { s1[tid] += s1[tid+o]; s2[tid] += s2[tid+o]; }
        __syncthreads();
    }
    if (tid == 0) {
        float inv = 1.f / (float)(BB*NPT);
        float m = s1[0] * inv;
        float var = s2[0] * inv - m*m;
        float rs = rsqrtf(var + EPSBN);
        scl[c] = g[c] * rs;
        shf[c] = beta[c] - m * g[c] * rs;
    }
}

__global__ void affine_relu_kernel(const float* __restrict__ Y, const float* __restrict__ scl,
                                   const float* __restrict__ shf, float* __restrict__ X, int Cc)
{
    int i = blockIdx.x * blockDim.x + threadIdx.x;  // float4 index
    int total = BB * Cc * (NPT/4);
    if (i >= total) return;
    int c = (i / (NPT/4)) % Cc;
    float4 v = ((const float4*)Y)[i];
    float sa = scl[c], sb = shf[c];
    v.x = fmaxf(fmaf(sa, v.x, sb), 0.f);
    v.y = fmaxf(fmaf(sa, v.y, sb), 0.f);
    v.z = fmaxf(fmaf(sa, v.z, sb), 0.f);
    v.w = fmaxf(fmaf(sa, v.w, sb), 0.f);
    ((float4*)X)[i] = v;
}

// ---------------- normalized features ----------------
__global__ void norm_head_kernel(const float* __restrict__ X, float* __restrict__ out)
{
    int idx = blockIdx.x * blockDim.x + threadIdx.x;
    if (idx >= BB*NPT) return;
    int b = idx / NPT, n = idx - b*NPT;
    float ss = 0.f;
    for (int c = 0; c < CCH; c++) {
        float v = X[((size_t)b*CCH + c)*NPT + n];
        ss += v*v;
    }
    float inv = 1.f / fmaxf(sqrtf(ss), 1e-12f);
    float* dst = out + BB*NPT;
    for (int c = 0; c < CCH; c++) {
        size_t oi = ((size_t)b*CCH + c)*NPT + n;
        dst[oi] = X[oi] * inv;
    }
}

// ======================= host launcher =======================
extern "C" void kernel_launch(void* const* d_in, const int* in_sizes, int n_in,
                              void* d_out, int out_size)
{
    const float* corr    = (const float*)d_in[0];
    const float* src     = (const float*)d_in[1];
    const float* tgt     = (const float*)d_in[2];
    const float* iW      = (const float*)d_in[3];
    const float* ib      = (const float*)d_in[4];
    const float* pcnW    = (const float*)d_in[5];
    const float* pcnb    = (const float*)d_in[6];
    const float* pcng    = (const float*)d_in[7];
    const float* pcnbeta = (const float*)d_in[8];
    const float* qW  = (const float*)d_in[9];  const float* qb  = (const float*)d_in[10];
    const float* kW  = (const float*)d_in[11]; const float* kb  = (const float*)d_in[12];
    const float* vW  = (const float*)d_in[13]; const float* vb  = (const float*)d_in[14];
    const float* m1W = (const float*)d_in[15]; const float* m1b = (const float*)d_in[16];
    const float* m1g = (const float*)d_in[17]; const float* m1beta = (const float*)d_in[18];
    const float* m2W = (const float*)d_in[19]; const float* m2b = (const float*)d_in[20];
    const float* m2g = (const float*)d_in[21]; const float* m2beta = (const float*)d_in[22];
    const float* m3W = (const float*)d_in[23]; const float* m3b = (const float*)d_in[24];
    const float* c1W = (const float*)d_in[25]; const float* c1b = (const float*)d_in[26];
    const float* c2W = (const float*)d_in[27]; const float* c2b = (const float*)d_in[28];
    const float* c3W = (const float*)d_in[29]; const float* c3b = (const float*)d_in[30];
    float* out = (float*)d_out;

    float *x, *y, *q, *k, *v, *h, *Mp, *P, *SC;
    float *scl, *shf, *scl1, *shf1, *scl2, *shf2;
    cudaGetSymbolAddress((void**)&x,   g_x);
    cudaGetSymbolAddress((void**)&y,   g_y);
    cudaGetSymbolAddress((void**)&q,   g_q);
    cudaGetSymbolAddress((void**)&k,   g_k);
    cudaGetSymbolAddress((void**)&v,   g_v);
    cudaGetSymbolAddress((void**)&h,   g_h);
    cudaGetSymbolAddress((void**)&Mp,  g_Mp);
    cudaGetSymbolAddress((void**)&P,   g_P);
    cudaGetSymbolAddress((void**)&SC,  g_SC);
    cudaGetSymbolAddress((void**)&scl,  g_scl);  cudaGetSymbolAddress((void**)&shf,  g_shf);
    cudaGetSymbolAddress((void**)&scl1, g_scl1); cudaGetSymbolAddress((void**)&shf1, g_shf1);
    cudaGetSymbolAddress((void**)&scl2, g_scl2); cudaGetSymbolAddress((void**)&shf2, g_shf2);

    const int nT64  = (NPT + 63) / 64;     // 47
    const int nT128 = (NPT + 127) / 128;   // 24
    dim3 blk(256);

    init_conv_kernel<<<(BB*NPT + 127)/128, 128>>>(corr, iW, ib, x);
    sc_kernel<<<dim3(nT128, nT128, BB), blk>>>(src, tgt, SC);

    for (int l = 0; l < LL; l++) {
        // PointCN: x = relu(bn(conv(x)))
        conv_kernel<0,false,false><<<dim3(nT64,2,BB), blk>>>(x, pcnW + (size_t)l*CCH*CCH, pcnb + l*CCH,
                                                             nullptr, nullptr, nullptr, y, CCH, CCH);
        bn_stats_kernel<<<CCH, 256>>>(y, pcng + l*CCH, pcnbeta + l*CCH, scl, shf, CCH);
        affine_relu_kernel<<<(BB*CCH*(NPT/4) + 255)/256, 256>>>(y, scl, shf, x, CCH);

        // Q, K, V projections
        conv_kernel<0,false,false><<<dim3(nT64,2,BB), blk>>>(x, qW + (size_t)l*CCH*CCH, qb + l*CCH,
                                                             nullptr, nullptr, nullptr, q, CCH, CCH);
        conv_kernel<0,false,false><<<dim3(nT64,2,BB), blk>>>(x, kW + (size_t)l*CCH*CCH, kb + l*CCH,
                                                             nullptr, nullptr, nullptr, k, CCH, CCH);
        conv_kernel<0,false,false><<<dim3(nT64,2,BB), blk>>>(x, vW + (size_t)l*CCH*CCH, vb + l*CCH,
                                                             nullptr, nullptr, nullptr, v, CCH, CCH);

        // attention
        gemm_scores_kernel<<<dim3(nT128, nT128, BB), blk>>>(q, k, SC, P);
        softmax_kernel<<<dim3(NPT, BB), blk>>>(P);
        gemm_msg_kernel<<<dim3(nT128, MSPLIT, BB), blk>>>(v, P, Mp);

        // msg MLP (BN affines fused into next conv's loads)
        conv_kernel<2,false,false><<<dim3(nT64,1,BB), blk>>>(Mp, m1W + (size_t)l*CH*CCH, m1b + l*CH,
                                                             nullptr, nullptr, nullptr, y, CCH, CH);
        bn_stats_kernel<<<CH, 256>>>(y, m1g + l*CH, m1beta + l*CH, scl1, shf1, CH);
        conv_kernel<1,false,false><<<dim3(nT64,1,BB), blk>>>(y, m2W + (size_t)l*CH*CH, m2b + l*CH,
                                                             scl1, shf1, nullptr, h, CH, CH);
        bn_stats_kernel<<<CH, 256>>>(h, m2g + l*CH, m2beta + l*CH, scl2, shf2, CH);
        conv_kernel<1,false,true><<<dim3(nT64,2,BB), blk>>>(h, m3W + (size_t)l*CCH*CH, m3b + l*CCH,
                                                            scl2, shf2, x, x, CH, CCH);
    }

    // outputs
    norm_head_kernel<<<(BB*NPT + 255)/256, 256>>>(x, out);
    conv_kernel<0,true,false><<<dim3(nT64,1,BB), blk>>>(x, c1W, c1b, nullptr, nullptr, nullptr, h, CCH, 32);
    conv_kernel<0,true,false><<<dim3(nT64,1,BB), blk>>>(h, c2W, c2b, nullptr, nullptr, nullptr, y, 32, 32);
    conv_kernel<0,false,false><<<dim3(nT64,1,BB), blk>>>(y, c3W, c3b, nullptr, nullptr, nullptr, out, 32, 1);
}

// round 8
// speedup vs baseline: 1.7265x; 1.7265x over previous
#include <cuda_runtime.h>
#include <math.h>

#define NPT 3000
#define BB 2
#define CCH 128
#define CH 64
#define LL 6
#define EPSBN 1e-5f
#define ATT_SCALE 0.08838834764831845f  // 1/sqrt(128)

#define TQ 64
#define TI 64
#define ISPLIT 3
#define SPLEN 1000
#define OPAD 3008
#define NEGBIG -1e30f

typedef unsigned long long ull;

__device__ __forceinline__ void ffma2(ull &d, ull a, ull b) {
    asm("fma.rn.f32x2 %0, %1, %2, %0;" : "+l"(d) : "l"(a), "l"(b));
}
__device__ __forceinline__ void mulf2(ull &d, ull f) {
    asm("mul.rn.f32x2 %0, %0, %1;" : "+l"(d) : "l"(f));
}
__device__ __forceinline__ float2 unp(ull v) {
    unsigned lo, hi;
    asm("mov.b64 {%0,%1}, %2;" : "=r"(lo), "=r"(hi) : "l"(v));
    return make_float2(__uint_as_float(lo), __uint_as_float(hi));
}
__device__ __forceinline__ ull packdup(float x) {
    ull r; unsigned u = __float_as_uint(x);
    asm("mov.b64 %0, {%1, %1};" : "=l"(r) : "r"(u));
    return r;
}
__device__ __forceinline__ ull d2u(double d) { return __double_as_longlong(d); }
__device__ __forceinline__ float sqrt_approx(float x) {
    float r; asm("sqrt.approx.f32 %0, %1;" : "=f"(r) : "f"(x)); return r;
}

// ---------------- device scratch ----------------
__device__ float g_x[BB*CCH*NPT];
__device__ float g_y[BB*CCH*NPT];
__device__ float g_q[BB*CCH*NPT];
__device__ float g_k[BB*CCH*NPT];
__device__ float g_v[BB*CCH*NPT];
__device__ float g_m[BB*CCH*NPT];
__device__ float g_h[BB*CCH*NPT];
__device__ float g_qt[(size_t)BB*NPT*CCH];
__device__ float g_kt[(size_t)BB*NPT*CCH];
__device__ float g_Op[(size_t)ISPLIT*BB*CCH*OPAD];
__device__ float g_Lp[ISPLIT*BB*OPAD];
__device__ float g_Mm[ISPLIT*BB*OPAD];
__device__ float g_scl[CCH],  g_shf[CCH];
__device__ float g_scl1[CCH], g_shf1[CCH];
__device__ float g_scl2[CCH], g_shf2[CCH];

// ---------------- init embedding ----------------
__global__ void init_conv_kernel(const float* __restrict__ corr, const float* __restrict__ W,
                                 const float* __restrict__ bias, float* __restrict__ X)
{
    __shared__ float Ws[CCH*6];
    __shared__ float bs[CCH];
    int tid = threadIdx.x;
    for (int i = tid; i < CCH*6; i += blockDim.x) Ws[i] = W[i];
    for (int i = tid; i < CCH;   i += blockDim.x) bs[i] = bias[i];
    __syncthreads();
    int idx = blockIdx.x * blockDim.x + tid;
    if (idx >= BB*NPT) return;
    int b = idx / NPT, n = idx - b*NPT;
    float cp[6];
#pragma unroll
    for (int j = 0; j < 6; j++) cp[j] = corr[(size_t)idx*6 + j];
    for (int co = 0; co < CCH; co++) {
        float a = bs[co];
#pragma unroll
        for (int j = 0; j < 6; j++) a += Ws[co*6 + j] * cp[j];
        X[((size_t)b*CCH + co)*NPT + n] = a;
    }
}

// ---------------- pointwise conv ----------------
// INMODE: 0 plain, 1 relu(scl*x+shf) on input
template<int INMODE, bool RELU, bool RESID>
__global__ void __launch_bounds__(256) conv_kernel(const float* __restrict__ X,
        const float* __restrict__ W, const float* __restrict__ bias,
        const float* __restrict__ scl, const float* __restrict__ shf,
        const float* __restrict__ R, float* __restrict__ Y, int Cin, int Cout)
{
    __shared__ float Ws[16][128];   // co duplicated
    __shared__ float Xs[16][64];
    __shared__ float sA[CCH], sB[CCH];
    int tid = threadIdx.x;
    int b = blockIdx.z, c0 = blockIdx.y << 6, n0 = blockIdx.x << 6;
    if (INMODE == 1) {
        if (tid < Cin) { sA[tid] = scl[tid]; sB[tid] = shf[tid]; }
    }
    int ty = tid >> 4, tx = tid & 15;
    ull acc[4][2];
#pragma unroll
    for (int i = 0; i < 4; i++) { acc[i][0] = 0ull; acc[i][1] = 0ull; }

#pragma unroll 1
    for (int kt = 0; kt < Cin; kt += 16) {
        __syncthreads();
        {
            int m = tid >> 2, kk4 = (tid & 3) << 2;
            float4 w = make_float4(0.f,0.f,0.f,0.f);
            if (c0 + m < Cout) w = *(const float4*)&W[(size_t)(c0 + m)*Cin + kt + kk4];
            Ws[kk4][2*m] = w.x;   Ws[kk4][2*m+1] = w.x;
            Ws[kk4+1][2*m] = w.y; Ws[kk4+1][2*m+1] = w.y;
            Ws[kk4+2][2*m] = w.z; Ws[kk4+2][2*m+1] = w.z;
            Ws[kk4+3][2*m] = w.w; Ws[kk4+3][2*m+1] = w.w;
        }
        {
            int kk = tid >> 4, j4 = (tid & 15) << 2;
            int ci = kt + kk;
            float4 v = make_float4(0.f,0.f,0.f,0.f);
            if (n0 + j4 < NPT) {
                v = *(const float4*)&X[((size_t)(b*Cin + ci))*NPT + n0 + j4];
                if (INMODE == 1) {
                    float sa = sA[ci], sb = sB[ci];
                    v.x = fmaxf(fmaf(sa, v.x, sb), 0.f);
                    v.y = fmaxf(fmaf(sa, v.y, sb), 0.f);
                    v.z = fmaxf(fmaf(sa, v.z, sb), 0.f);
                    v.w = fmaxf(fmaf(sa, v.w, sb), 0.f);
                }
            }
            *(float4*)&Xs[kk][j4] = v;
        }
        __syncthreads();
#pragma unroll
        for (int kk = 0; kk < 16; kk++) {
            const double2* wp = (const double2*)&Ws[kk][ty << 3];
            double2 w0 = wp[0], w1 = wp[1];
            ull a[4] = {d2u(w0.x), d2u(w0.y), d2u(w1.x), d2u(w1.y)};
            const double2* xp = (const double2*)&Xs[kk][tx << 2];
            double2 x0 = xp[0];
            ull b0 = d2u(x0.x), b1 = d2u(x0.y);
#pragma unroll
            for (int mi = 0; mi < 4; mi++) {
                ffma2(acc[mi][0], a[mi], b0);
                ffma2(acc[mi][1], a[mi], b1);
            }
        }
    }

    int n = n0 + (tx << 2);
    if (n >= NPT) return;
#pragma unroll
    for (int mi = 0; mi < 4; mi++) {
        int co = c0 + (ty << 2) + mi;
        if (co >= Cout) continue;
        float bv = bias[co];
        float2 f0 = unp(acc[mi][0]), f1 = unp(acc[mi][1]);
        float4 o4 = make_float4(f0.x + bv, f0.y + bv, f1.x + bv, f1.y + bv);
        size_t off = ((size_t)(b*Cout + co))*NPT + n;
        if (RESID) {
            float4 r = *(const float4*)&R[off];
            o4.x += r.x; o4.y += r.y; o4.z += r.z; o4.w += r.w;
        }
        if (RELU) {
            o4.x = fmaxf(o4.x, 0.f); o4.y = fmaxf(o4.y, 0.f);
            o4.z = fmaxf(o4.z, 0.f); o4.w = fmaxf(o4.w, 0.f);
        }
        *(float4*)&Y[off] = o4;
    }
}

// ---------------- BN stats -> per-channel affine ----------------
__global__ void bn_stats_kernel(const float* __restrict__ Y, const float* __restrict__ g,
                                const float* __restrict__ beta, float* __restrict__ scl,
                                float* __restrict__ shf, int Cc)
{
    __shared__ float s1[256], s2[256];
    int c = blockIdx.x, tid = threadIdx.x;
    float a = 0.f, q = 0.f;
    for (int bb = 0; bb < BB; bb++) {
        const float* row = Y + ((size_t)(bb*Cc + c))*NPT;
        for (int i = tid*4; i < NPT; i += 1024) {
            float4 v = *(const float4*)&row[i];
            a += v.x + v.y + v.z + v.w;
            q += v.x*v.x + v.y*v.y + v.z*v.z + v.w*v.w;
        }
    }
    s1[tid] = a; s2[tid] = q;
    __syncthreads();
    for (int o = 128; o > 0; o >>= 1) {
        if (tid < o) { s1[tid] += s1[tid+o]; s2[tid] += s2[tid+o]; }
        __syncthreads();
    }
    if (tid == 0) {
        float inv = 1.f / (float)(BB*NPT);
        float m = s1[0] * inv;
        float var = s2[0] * inv - m*m;
        float rs = rsqrtf(var + EPSBN);
        scl[c] = g[c] * rs;
        shf[c] = beta[c] - m * g[c] * rs;
    }
}

__global__ void affine_relu_kernel(const float* __restrict__ Y, const float* __restrict__ scl,
                                   const float* __restrict__ shf, float* __restrict__ X, int Cc)
{
    int i = blockIdx.x * blockDim.x + threadIdx.x;  // float4 index
    int total = BB * Cc * (NPT/4);
    if (i >= total) return;
    int c = (i / (NPT/4)) % Cc;
    float4 v = ((const float4*)Y)[i];
    float sa = scl[c], sb = shf[c];
    v.x = fmaxf(fmaf(sa, v.x, sb), 0.f);
    v.y = fmaxf(fmaf(sa, v.y, sb), 0.f);
    v.z = fmaxf(fmaf(sa, v.z, sb), 0.f);
    v.w = fmaxf(fmaf(sa, v.w, sb), 0.f);
    ((float4*)X)[i] = v;
}

// ---------------- transpose [b][c][n] -> [b][n][c] ----------------
__global__ void tr_kernel(const float* __restrict__ in, float* __restrict__ out)
{
    __shared__ float tile[32][33];
    int tid = threadIdx.x;
    int tx = tid & 31, ty = tid >> 5;   // 32 x 8
    int n0 = blockIdx.x << 5, c0 = blockIdx.y << 5, b = blockIdx.z;
#pragma unroll
    for (int k = 0; k < 4; k++) {
        int c = c0 + ty + (k << 3);
        int n = n0 + tx;
        tile[ty + (k << 3)][tx] = (n < NPT) ? in[((size_t)(b*CCH + c))*NPT + n] : 0.f;
    }
    __syncthreads();
#pragma unroll
    for (int k = 0; k < 4; k++) {
        int n = n0 + ty + (k << 3);
        int c = c0 + tx;
        if (n < NPT) out[((size_t)b*NPT + n)*CCH + c] = tile[tx][ty + (k << 3)];
    }
}

// ---------------- flash attention ----------------
struct FlashS {
    float Qt[TQ][132];
    float Kt[TI][132];
    float Vs[CCH][TI];
    float Pd[TQ][68];
    float pI[TI][6];
    float alph[TQ];
};

__global__ void __launch_bounds__(512, 1) flash_kernel(
    const float* __restrict__ Qt, const float* __restrict__ Kt,
    const float* __restrict__ V,
    const float* __restrict__ src, const float* __restrict__ tgt,
    float* __restrict__ Op, float* __restrict__ Lp, float* __restrict__ Mm)
{
    extern __shared__ char smem_raw[];
    FlashS& S = *reinterpret_cast<FlashS*>(smem_raw);
    int tid = threadIdx.x;
    int otile = blockIdx.x * TQ;
    int sp = blockIdx.y, b = blockIdx.z;
    int sbase = sp * SPLEN;
    int send  = min(sbase + SPLEN, NPT);

    // S-phase map: og (o pair), tx (i, strided 16)
    int og = tid >> 4;       // 0..31
    int tx = tid & 15;
    int o0 = og << 1;
    // AV map: cg (4 c), ox (o, strided 16)
    int cg = tid >> 4;
    int ox = tid & 15;

    // ---- prologue: Q tile + per-thread o keypoints ----
#pragma unroll
    for (int j = 0; j < 4; j++) {
        int idx = tid + (j << 9);
        int row = idx >> 5, c4 = (idx & 31) << 2;
        int go = otile + row;
        float4 qv = make_float4(0.f,0.f,0.f,0.f);
        if (go < NPT) qv = *(const float4*)&Qt[((size_t)b*NPT + go)*CCH + c4];
        *(float4*)&S.Qt[row][c4] = qv;
    }
    float pO[2][6];
#pragma unroll
    for (int oo = 0; oo < 2; oo++) {
        int go = otile + o0 + oo;
        if (go < NPT) {
#pragma unroll
            for (int e = 0; e < 3; e++) {
                pO[oo][e]   = src[((size_t)b*NPT + go)*3 + e];
                pO[oo][3+e] = tgt[((size_t)b*NPT + go)*3 + e];
            }
        } else {
#pragma unroll
            for (int e = 0; e < 6; e++) pO[oo][e] = 0.f;
        }
    }
    float mr[2] = {NEGBIG, NEGBIG};
    float lr[2] = {0.f, 0.f};
    ull accO[4][4];
#pragma unroll
    for (int i = 0; i < 4; i++)
#pragma unroll
        for (int j = 0; j < 4; j++) accO[i][j] = 0ull;

    const int nch = (send - sbase + TI - 1) / TI;
#pragma unroll 1
    for (int ch = 0; ch < nch; ch++) {
        int ibase = sbase + ch * TI;
        __syncthreads();
        // fill K chunk transposed [i][c]
#pragma unroll
        for (int j = 0; j < 4; j++) {
            int idx = tid + (j << 9);
            int row = idx >> 5, c4 = (idx & 31) << 2;
            int gi = ibase + row;
            float4 kv = make_float4(0.f,0.f,0.f,0.f);
            if (gi < send) kv = *(const float4*)&Kt[((size_t)b*NPT + gi)*CCH + c4];
            *(float4*)&S.Kt[row][c4] = kv;
        }
        // fill V chunk [c][i]
#pragma unroll
        for (int j = 0; j < 4; j++) {
            int idx = tid + (j << 9);
            int c = idx >> 4, i4 = (idx & 15) << 2;
            int gi = ibase + i4;
            float4 vv = make_float4(0.f,0.f,0.f,0.f);
            if (gi < send) vv = *(const float4*)&V[((size_t)(b*CCH + c))*NPT + gi];
            *(float4*)&S.Vs[c][i4] = vv;
        }
        // fill i keypoints
        if (tid < TI) {
            int gi = ibase + tid;
            if (gi < send) {
#pragma unroll
                for (int e = 0; e < 3; e++) {
                    S.pI[tid][e]   = src[((size_t)b*NPT + gi)*3 + e];
                    S.pI[tid][3+e] = tgt[((size_t)b*NPT + gi)*3 + e];
                }
            } else {
#pragma unroll
                for (int e = 0; e < 6; e++) S.pI[tid][e] = 0.f;
            }
        }
        __syncthreads();

        // ---- S = Q^T K (reduction-packed pairs over c) ----
        ull sacc[2][4];
#pragma unroll
        for (int i = 0; i < 2; i++)
#pragma unroll
            for (int j = 0; j < 4; j++) sacc[i][j] = 0ull;
#pragma unroll 4
        for (int cq = 0; cq < CCH; cq += 4) {
            double2 a0 = *(const double2*)&S.Qt[o0][cq];
            double2 a1 = *(const double2*)&S.Qt[o0+1][cq];
            ull a00 = d2u(a0.x), a01 = d2u(a0.y);
            ull a10 = d2u(a1.x), a11 = d2u(a1.y);
#pragma unroll
            for (int ik = 0; ik < 4; ik++) {
                double2 bq = *(const double2*)&S.Kt[tx + (ik << 4)][cq];
                ull b01 = d2u(bq.x), b23 = d2u(bq.y);
                ffma2(sacc[0][ik], a00, b01);
                ffma2(sacc[0][ik], a01, b23);
                ffma2(sacc[1][ik], a10, b01);
                ffma2(sacc[1][ik], a11, b23);
            }
        }

        // ---- softmax epilogue ----
        float sv[2][4];
#pragma unroll
        for (int oo = 0; oo < 2; oo++)
#pragma unroll
            for (int ik = 0; ik < 4; ik++) {
                float2 f = unp(sacc[oo][ik]);
                sv[oo][ik] = f.x + f.y;
            }
#pragma unroll
        for (int ik = 0; ik < 4; ik++) {
            int il = tx + (ik << 4);
            int gi = ibase + il;
            bool valid = gi < send;
            float pi0 = S.pI[il][0], pi1 = S.pI[il][1], pi2 = S.pI[il][2];
            float pi3 = S.pI[il][3], pi4 = S.pI[il][4], pi5 = S.pI[il][5];
#pragma unroll
            for (int oo = 0; oo < 2; oo++) {
                float dx = pO[oo][0] - pi0, dy = pO[oo][1] - pi1, dz = pO[oo][2] - pi2;
                float ds = sqrt_approx(dx*dx + dy*dy + dz*dz);
                dx = pO[oo][3] - pi3; dy = pO[oo][4] - pi4; dz = pO[oo][5] - pi5;
                float dt = sqrt_approx(dx*dx + dy*dy + dz*dz);
                float d = ds - dt;
                float scv = fmaxf(1.f - d*d, 0.f) * ATT_SCALE;
                sv[oo][ik] = valid ? sv[oo][ik] * scv : NEGBIG;
            }
        }
#pragma unroll
        for (int oo = 0; oo < 2; oo++) {
            float mx = fmaxf(fmaxf(sv[oo][0], sv[oo][1]), fmaxf(sv[oo][2], sv[oo][3]));
#pragma unroll
            for (int s = 8; s; s >>= 1) mx = fmaxf(mx, __shfl_xor_sync(0xffffffffu, mx, s, 16));
            float mnew = fmaxf(mr[oo], mx);
            float al = __expf(mr[oo] - mnew);
            mr[oo] = mnew;
            float psum = 0.f;
#pragma unroll
            for (int ik = 0; ik < 4; ik++) {
                float p = __expf(sv[oo][ik] - mnew);
                S.Pd[o0 + oo][tx + (ik << 4)] = p;
                psum += p;
            }
#pragma unroll
            for (int s = 8; s; s >>= 1) psum += __shfl_xor_sync(0xffffffffu, psum, s, 16);
            lr[oo] = lr[oo] * al + psum;
            if (tx == 0) S.alph[o0 + oo] = al;
        }
        __syncthreads();

        // ---- AV: rescale then accumulate ----
#pragma unroll
        for (int ok = 0; ok < 4; ok++) {
            float al = S.alph[ox + (ok << 4)];
            ull ad = packdup(al);
#pragma unroll
            for (int cc = 0; cc < 4; cc++) mulf2(accO[cc][ok], ad);
        }
        int c0 = cg << 2;
#pragma unroll 2
        for (int iq = 0; iq < TI; iq += 4) {
            double2 av[4], bv[4];
#pragma unroll
            for (int cc = 0; cc < 4; cc++) av[cc] = *(const double2*)&S.Vs[c0 + cc][iq];
#pragma unroll
            for (int ok = 0; ok < 4; ok++) bv[ok] = *(const double2*)&S.Pd[ox + (ok << 4)][iq];
#pragma unroll
            for (int cc = 0; cc < 4; cc++) {
                ull ax = d2u(av[cc].x), ay = d2u(av[cc].y);
#pragma unroll
                for (int ok = 0; ok < 4; ok++) {
                    ffma2(accO[cc][ok], ax, d2u(bv[ok].x));
                    ffma2(accO[cc][ok], ay, d2u(bv[ok].y));
                }
            }
        }
    }

    // ---- epilogue: write partials ----
    int c0 = cg << 2;
#pragma unroll
    for (int cc = 0; cc < 4; cc++)
#pragma unroll
        for (int ok = 0; ok < 4; ok++) {
            float2 f = unp(accO[cc][ok]);
            float val = f.x + f.y;
            int go = otile + ox + (ok << 4);
            if (go < NPT)
                Op[((size_t)((sp*BB + b)*CCH + c0 + cc))*OPAD + go] = val;
        }
    if (tx == 0) {
#pragma unroll
        for (int oo = 0; oo < 2; oo++) {
            int go = otile + o0 + oo;
            if (go < NPT) {
                Mm[(sp*BB + b)*OPAD + go] = mr[oo];
                Lp[(sp*BB + b)*OPAD + go] = lr[oo];
            }
        }
    }
}

// ---------------- merge split partials -> msg [b][c][o] ----------------
__global__ void merge_kernel(const float* __restrict__ Op, const float* __restrict__ Lp,
                             const float* __restrict__ Mm, float* __restrict__ M)
{
    const int NO4 = NPT / 4;
    int t = blockIdx.x * blockDim.x + threadIdx.x;
    if (t >= BB*CCH*NO4) return;
    int o4 = (t % NO4) << 2;
    int bc = t / NO4;
    int b = bc / CCH, c = bc % CCH;

    float mv[ISPLIT][4], lv[ISPLIT][4], xv[ISPLIT][4];
#pragma unroll
    for (int s = 0; s < ISPLIT; s++) {
        *(float4*)mv[s] = *(const float4*)&Mm[(s*BB + b)*OPAD + o4];
        *(float4*)lv[s] = *(const float4*)&Lp[(s*BB + b)*OPAD + o4];
        *(float4*)xv[s] = *(const float4*)&Op[((size_t)((s*BB + b)*CCH + c))*OPAD + o4];
    }
    float res[4];
#pragma unroll
    for (int j = 0; j < 4; j++) {
        float Mx = mv[0][j];
#pragma unroll
        for (int s = 1; s < ISPLIT; s++) Mx = fmaxf(Mx, mv[s][j]);
        float L = 0.f, num = 0.f;
#pragma unroll
        for (int s = 0; s < ISPLIT; s++) {
            float w = __expf(mv[s][j] - Mx);
            L   += lv[s][j] * w;
            num += xv[s][j] * w;
        }
        res[j] = num / L;
    }
    *(float4*)&M[((size_t)(b*CCH + c))*NPT + o4] = *(float4*)res;
}

// ---------------- normalized features ----------------
__global__ void norm_head_kernel(const float* __restrict__ X, float* __restrict__ out)
{
    int idx = blockIdx.x * blockDim.x + threadIdx.x;
    if (idx >= BB*NPT) return;
    int b = idx / NPT, n = idx - b*NPT;
    float ss = 0.f;
    for (int c = 0; c < CCH; c++) {
        float v = X[((size_t)b*CCH + c)*NPT + n];
        ss += v*v;
    }
    float inv = 1.f / fmaxf(sqrtf(ss), 1e-12f);
    float* dst = out + BB*NPT;
    for (int c = 0; c < CCH; c++) {
        size_t oi = ((size_t)b*CCH + c)*NPT + n;
        dst[oi] = X[oi] * inv;
    }
}

// ======================= host launcher =======================
extern "C" void kernel_launch(void* const* d_in, const int* in_sizes, int n_in,
                              void* d_out, int out_size)
{
    const float* corr    = (const float*)d_in[0];
    const float* src     = (const float*)d_in[1];
    const float* tgt     = (const float*)d_in[2];
    const float* iW      = (const float*)d_in[3];
    const float* ib      = (const float*)d_in[4];
    const float* pcnW    = (const float*)d_in[5];
    const float* pcnb    = (const float*)d_in[6];
    const float* pcng    = (const float*)d_in[7];
    const float* pcnbeta = (const float*)d_in[8];
    const float* qW  = (const float*)d_in[9];  const float* qb  = (const float*)d_in[10];
    const float* kW  = (const float*)d_in[11]; const float* kb  = (const float*)d_in[12];
    const float* vW  = (const float*)d_in[13]; const float* vb  = (const float*)d_in[14];
    const float* m1W = (const float*)d_in[15]; const float* m1b = (const float*)d_in[16];
    const float* m1g = (const float*)d_in[17]; const float* m1beta = (const float*)d_in[18];
    const float* m2W = (const float*)d_in[19]; const float* m2b = (const float*)d_in[20];
    const float* m2g = (const float*)d_in[21]; const float* m2beta = (const float*)d_in[22];
    const float* m3W = (const float*)d_in[23]; const float* m3b = (const float*)d_in[24];
    const float* c1W = (const float*)d_in[25]; const float* c1b = (const float*)d_in[26];
    const float* c2W = (const float*)d_in[27]; const float* c2b = (const float*)d_in[28];
    const float* c3W = (const float*)d_in[29]; const float* c3b = (const float*)d_in[30];
    float* out = (float*)d_out;

    float *x, *y, *q, *k, *v, *m, *h, *qt, *kt, *Op, *Lp, *Mm;
    float *scl, *shf, *scl1, *shf1, *scl2, *shf2;
    cudaGetSymbolAddress((void**)&x,  g_x);
    cudaGetSymbolAddress((void**)&y,  g_y);
    cudaGetSymbolAddress((void**)&q,  g_q);
    cudaGetSymbolAddress((void**)&k,  g_k);
    cudaGetSymbolAddress((void**)&v,  g_v);
    cudaGetSymbolAddress((void**)&m,  g_m);
    cudaGetSymbolAddress((void**)&h,  g_h);
    cudaGetSymbolAddress((void**)&qt, g_qt);
    cudaGetSymbolAddress((void**)&kt, g_kt);
    cudaGetSymbolAddress((void**)&Op, g_Op);
    cudaGetSymbolAddress((void**)&Lp, g_Lp);
    cudaGetSymbolAddress((void**)&Mm, g_Mm);
    cudaGetSymbolAddress((void**)&scl,  g_scl);  cudaGetSymbolAddress((void**)&shf,  g_shf);
    cudaGetSymbolAddress((void**)&scl1, g_scl1); cudaGetSymbolAddress((void**)&shf1, g_shf1);
    cudaGetSymbolAddress((void**)&scl2, g_scl2); cudaGetSymbolAddress((void**)&shf2, g_shf2);

    const int nT64 = (NPT + 63) / 64;        // 47
    const int nT32 = (NPT + 31) / 32;        // 94
    const int smemFlash = (int)sizeof(FlashS);
    cudaFuncSetAttribute(flash_kernel, cudaFuncAttributeMaxDynamicSharedMemorySize, smemFlash);

    dim3 blk(256);
    init_conv_kernel<<<(BB*NPT + 127)/128, 128>>>(corr, iW, ib, x);

    for (int l = 0; l < LL; l++) {
        // PointCN: x = relu(bn(conv(x)))
        conv_kernel<0,false,false><<<dim3(nT64,2,BB), blk>>>(x, pcnW + (size_t)l*CCH*CCH, pcnb + l*CCH,
                                                             nullptr, nullptr, nullptr, y, CCH, CCH);
        bn_stats_kernel<<<CCH, 256>>>(y, pcng + l*CCH, pcnbeta + l*CCH, scl, shf, CCH);
        affine_relu_kernel<<<(BB*CCH*(NPT/4) + 255)/256, 256>>>(y, scl, shf, x, CCH);

        // Q, K, V projections
        conv_kernel<0,false,false><<<dim3(nT64,2,BB), blk>>>(x, qW + (size_t)l*CCH*CCH, qb + l*CCH,
                                                             nullptr, nullptr, nullptr, q, CCH, CCH);
        conv_kernel<0,false,false><<<dim3(nT64,2,BB), blk>>>(x, kW + (size_t)l*CCH*CCH, kb + l*CCH,
                                                             nullptr, nullptr, nullptr, k, CCH, CCH);
        conv_kernel<0,false,false><<<dim3(nT64,2,BB), blk>>>(x, vW + (size_t)l*CCH*CCH, vb + l*CCH,
                                                             nullptr, nullptr, nullptr, v, CCH, CCH);
        // transpose Q, K to [n][c]
        tr_kernel<<<dim3(nT32,4,BB), blk>>>(q, qt);
        tr_kernel<<<dim3(nT32,4,BB), blk>>>(k, kt);

        // flash attention + merge
        flash_kernel<<<dim3(nT64, ISPLIT, BB), 512, smemFlash>>>(qt, kt, v, src, tgt, Op, Lp, Mm);
        merge_kernel<<<(BB*CCH*(NPT/4) + 255)/256, 256>>>(Op, Lp, Mm, m);

        // msg MLP (BN affines fused into next conv's loads)
        conv_kernel<0,false,false><<<dim3(nT64,1,BB), blk>>>(m, m1W + (size_t)l*CH*CCH, m1b + l*CH,
                                                             nullptr, nullptr, nullptr, y, CCH, CH);
        bn_stats_kernel<<<CH, 256>>>(y, m1g + l*CH, m1beta + l*CH, scl1, shf1, CH);
        conv_kernel<1,false,false><<<dim3(nT64,1,BB), blk>>>(y, m2W + (size_t)l*CH*CH, m2b + l*CH,
                                                             scl1, shf1, nullptr, h, CH, CH);
        bn_stats_kernel<<<CH, 256>>>(h, m2g + l*CH, m2beta + l*CH, scl2, shf2, CH);
        conv_kernel<1,false,true><<<dim3(nT64,2,BB), blk>>>(h, m3W + (size_t)l*CCH*CH, m3b + l*CCH,
                                                            scl2, shf2, x, x, CH, CCH);
    }

    // outputs
    norm_head_kernel<<<(BB*NPT + 255)/256, 256>>>(x, out);
    conv_kernel<0,true,false><<<dim3(nT64,1,BB), blk>>>(x, c1W, c1b, nullptr, nullptr, nullptr, h, CCH, 32);
    conv_kernel<0,true,false><<<dim3(nT64,1,BB), blk>>>(h, c2W, c2b, nullptr, nullptr, nullptr, y, 32, 32);
    conv_kernel<0,false,false><<<dim3(nT64,1,BB), blk>>>(y, c3W, c3b, nullptr, nullptr, nullptr, out, 32, 1);
}

// round 10
// speedup vs baseline: 1.7418x; 1.0089x over previous
#include <cuda_runtime.h>
#include <math.h>

#define NPT 3000
#define BB 2
#define CCH 128
#define CH 64
#define LL 6
#define EPSBN 1e-5f
#define ATT_SCALE 0.08838834764831845f  // 1/sqrt(128)

#define TQ 64
#define TI 64
#define ISPLIT 3
#define SPLEN 1000
#define OPAD 3008
#define NEGBIG -1e30f

typedef unsigned long long ull;

__device__ __forceinline__ void ffma2(ull &d, ull a, ull b) {
    asm("fma.rn.f32x2 %0, %1, %2, %0;" : "+l"(d) : "l"(a), "l"(b));
}
__device__ __forceinline__ void mulf2(ull &d, ull f) {
    asm("mul.rn.f32x2 %0, %0, %1;" : "+l"(d) : "l"(f));
}
__device__ __forceinline__ float2 unp(ull v) {
    unsigned lo, hi;
    asm("mov.b64 {%0,%1}, %2;" : "=r"(lo), "=r"(hi) : "l"(v));
    return make_float2(__uint_as_float(lo), __uint_as_float(hi));
}
__device__ __forceinline__ ull packdup(float x) {
    ull r; unsigned u = __float_as_uint(x);
    asm("mov.b64 %0, {%1, %1};" : "=l"(r) : "r"(u));
    return r;
}
__device__ __forceinline__ ull d2u(double d) { return __double_as_longlong(d); }
__device__ __forceinline__ float sqrt_approx(float x) {
    float r; asm("sqrt.approx.f32 %0, %1;" : "=f"(r) : "f"(x)); return r;
}

// ---------------- device scratch ----------------
__device__ float g_x[BB*CCH*NPT];
__device__ float g_y[BB*CCH*NPT];
__device__ float g_v[BB*CCH*NPT];
__device__ float g_m[BB*CCH*NPT];
__device__ float g_h[BB*CCH*NPT];
__device__ float g_qt[(size_t)BB*NPT*CCH];
__device__ float g_kt[(size_t)BB*NPT*CCH];
__device__ float g_Op[(size_t)ISPLIT*BB*CCH*OPAD];
__device__ float g_Lp[ISPLIT*BB*OPAD];
__device__ float g_Mm[ISPLIT*BB*OPAD];
__device__ float g_wc[ISPLIT*BB*OPAD];
__device__ float g_ps[CCH*96], g_pq[CCH*96];
__device__ float g_scl[CCH],  g_shf[CCH];
__device__ float g_scl1[CCH], g_shf1[CCH];
__device__ float g_scl2[CCH], g_shf2[CCH];

// ---------------- init embedding ----------------
__global__ void init_conv_kernel(const float* __restrict__ corr, const float* __restrict__ W,
                                 const float* __restrict__ bias, float* __restrict__ X)
{
    __shared__ float Ws[CCH*6];
    __shared__ float bs[CCH];
    int tid = threadIdx.x;
    for (int i = tid; i < CCH*6; i += blockDim.x) Ws[i] = W[i];
    for (int i = tid; i < CCH;   i += blockDim.x) bs[i] = bias[i];
    __syncthreads();
    int idx = blockIdx.x * blockDim.x + tid;
    if (idx >= BB*NPT) return;
    int b = idx / NPT, n = idx - b*NPT;
    float cp[6];
#pragma unroll
    for (int j = 0; j < 6; j++) cp[j] = corr[(size_t)idx*6 + j];
    for (int co = 0; co < CCH; co++) {
        float a = bs[co];
#pragma unroll
        for (int j = 0; j < 6; j++) a += Ws[co*6 + j] * cp[j];
        X[((size_t)b*CCH + co)*NPT + n] = a;
    }
}

// ---------------- pointwise conv ----------------
// INMODE: 0 plain, 1 relu(scl*x+shf) on input, 3 weighted 3-way Op merge
// RES:    0 none, 1 plain residual, 2 residual r -> relu(rscl*r+rshf)
// TROUT:  store output as [n][c] (requires Cout tile within CCH row)
// STATS:  emit per-(c, block) partial sum/sumsq of (pre-relu, post-bias) output
template<int INMODE, bool RELU, int RES, bool TROUT, bool STATS>
__global__ void __launch_bounds__(256) conv_kernel(const float* __restrict__ X,
        const float* __restrict__ W, const float* __restrict__ bias,
        const float* __restrict__ scl, const float* __restrict__ shf,
        const float* __restrict__ R, const float* __restrict__ rscl,
        const float* __restrict__ rshf, const float* __restrict__ wc,
        float* __restrict__ Y, float* __restrict__ psum, float* __restrict__ psq,
        int Cin, int Cout)
{
    __shared__ float Ws[16][128];   // co duplicated
    __shared__ float Xs[16][64];
    __shared__ float sA[CCH], sB[CCH];
    __shared__ float swc[ISPLIT][64];
    int tid = threadIdx.x;
    int b = blockIdx.z, c0 = blockIdx.y << 6, n0 = blockIdx.x << 6;
    if (INMODE == 1) {
        if (tid < Cin) { sA[tid] = scl[tid]; sB[tid] = shf[tid]; }
    }
    if (INMODE == 3) {
        if (tid < ISPLIT*64) {
            int s = tid >> 6, j = tid & 63;
            int n = n0 + j;
            swc[s][j] = (n < NPT) ? wc[(s*BB + b)*OPAD + n] : 0.f;
        }
    }
    int ty = tid >> 4, tx = tid & 15;
    ull acc[4][2];
#pragma unroll
    for (int i = 0; i < 4; i++) { acc[i][0] = 0ull; acc[i][1] = 0ull; }

#pragma unroll 1
    for (int kt = 0; kt < Cin; kt += 16) {
        __syncthreads();
        {
            int m = tid >> 2, kk4 = (tid & 3) << 2;
            float4 w = make_float4(0.f,0.f,0.f,0.f);
            if (c0 + m < Cout) w = *(const float4*)&W[(size_t)(c0 + m)*Cin + kt + kk4];
            Ws[kk4][2*m] = w.x;   Ws[kk4][2*m+1] = w.x;
            Ws[kk4+1][2*m] = w.y; Ws[kk4+1][2*m+1] = w.y;
            Ws[kk4+2][2*m] = w.z; Ws[kk4+2][2*m+1] = w.z;
            Ws[kk4+3][2*m] = w.w; Ws[kk4+3][2*m+1] = w.w;
        }
        {
            int kk = tid >> 4, j4 = (tid & 15) << 2;
            int ci = kt + kk;
            float4 v = make_float4(0.f,0.f,0.f,0.f);
            if (INMODE == 3) {
                const size_t sstr = (size_t)BB*CCH*OPAD;
                const float* base = X + ((size_t)(b*CCH + ci))*OPAD + n0 + j4;
                float4 a0 = *(const float4*)&base[0];
                float4 a1 = *(const float4*)&base[sstr];
                float4 a2 = *(const float4*)&base[2*sstr];
                float w00 = swc[0][j4],   w01 = swc[0][j4+1], w02 = swc[0][j4+2], w03 = swc[0][j4+3];
                float w10 = swc[1][j4],   w11 = swc[1][j4+1], w12 = swc[1][j4+2], w13 = swc[1][j4+3];
                float w20 = swc[2][j4],   w21 = swc[2][j4+1], w22 = swc[2][j4+2], w23 = swc[2][j4+3];
                v.x = a0.x*w00 + a1.x*w10 + a2.x*w20;
                v.y = a0.y*w01 + a1.y*w11 + a2.y*w21;
                v.z = a0.z*w02 + a1.z*w12 + a2.z*w22;
                v.w = a0.w*w03 + a1.w*w13 + a2.w*w23;
            } else if (n0 + j4 < NPT) {
                v = *(const float4*)&X[((size_t)(b*Cin + ci))*NPT + n0 + j4];
                if (INMODE == 1) {
                    float sa = sA[ci], sb = sB[ci];
                    v.x = fmaxf(fmaf(sa, v.x, sb), 0.f);
                    v.y = fmaxf(fmaf(sa, v.y, sb), 0.f);
                    v.z = fmaxf(fmaf(sa, v.z, sb), 0.f);
                    v.w = fmaxf(fmaf(sa, v.w, sb), 0.f);
                }
            }
            *(float4*)&Xs[kk][j4] = v;
        }
        __syncthreads();
#pragma unroll
        for (int kk = 0; kk < 16; kk++) {
            const double2* wp = (const double2*)&Ws[kk][ty << 3];
            double2 w0 = wp[0], w1 = wp[1];
            ull a[4] = {d2u(w0.x), d2u(w0.y), d2u(w1.x), d2u(w1.y)};
            const double2* xp = (const double2*)&Xs[kk][tx << 2];
            double2 x0 = xp[0];
            ull b0 = d2u(x0.x), b1 = d2u(x0.y);
#pragma unroll
            for (int mi = 0; mi < 4; mi++) {
                ffma2(acc[mi][0], a[mi], b0);
                ffma2(acc[mi][1], a[mi], b1);
            }
        }
    }

    // -------- epilogue --------
    int n = n0 + (tx << 2);
    bool nv[4];
#pragma unroll
    for (int j = 0; j < 4; j++) nv[j] = (n + j < NPT);
    float vals[4][4];
#pragma unroll
    for (int mi = 0; mi < 4; mi++) {
        int co = c0 + (ty << 2) + mi;
        float bv = (co < Cout) ? bias[co] : 0.f;
        float2 f0 = unp(acc[mi][0]), f1 = unp(acc[mi][1]);
        vals[mi][0] = f0.x + bv; vals[mi][1] = f0.y + bv;
        vals[mi][2] = f1.x + bv; vals[mi][3] = f1.y + bv;
    }

    if (STATS) {
#pragma unroll
        for (int mi = 0; mi < 4; mi++) {
            float s = 0.f, sq = 0.f;
#pragma unroll
            for (int j = 0; j < 4; j++)
                if (nv[j]) { s += vals[mi][j]; sq += vals[mi][j]*vals[mi][j]; }
#pragma unroll
            for (int o = 8; o; o >>= 1) {
                s  += __shfl_xor_sync(0xffffffffu, s,  o, 16);
                sq += __shfl_xor_sync(0xffffffffu, sq, o, 16);
            }
            if (tx == 0) {
                int co = c0 + (ty << 2) + mi;
                if (co < Cout) {
                    int p = b*47 + blockIdx.x;
                    psum[co*96 + p] = s;
                    psq[co*96 + p]  = sq;
                }
            }
        }
    }

    if (TROUT) {
        float* base = Y + (size_t)b*NPT*CCH;
        int cb = c0 + (ty << 2);
#pragma unroll
        for (int j = 0; j < 4; j++) {
            if (!nv[j]) continue;
            *(float4*)&base[(size_t)(n + j)*CCH + cb] =
                make_float4(vals[0][j], vals[1][j], vals[2][j], vals[3][j]);
        }
    } else {
#pragma unroll
        for (int mi = 0; mi < 4; mi++) {
            int co = c0 + (ty << 2) + mi;
            if (co >= Cout) continue;
            float4 o4 = make_float4(vals[mi][0], vals[mi][1], vals[mi][2], vals[mi][3]);
            size_t off = ((size_t)(b*Cout + co))*NPT + n;
            if (!nv[0]) continue;   // whole float4 invalid only when n>=NPT
            if (RES) {
                float4 r = *(const float4*)&R[off];
                if (RES == 2) {
                    float ra = rscl[co], rb = rshf[co];
                    r.x = fmaxf(fmaf(ra, r.x, rb), 0.f);
                    r.y = fmaxf(fmaf(ra, r.y, rb), 0.f);
                    r.z = fmaxf(fmaf(ra, r.z, rb), 0.f);
                    r.w = fmaxf(fmaf(ra, r.w, rb), 0.f);
                }
                o4.x += r.x; o4.y += r.y; o4.z += r.z; o4.w += r.w;
            }
            if (RELU) {
                o4.x = fmaxf(o4.x, 0.f); o4.y = fmaxf(o4.y, 0.f);
                o4.z = fmaxf(o4.z, 0.f); o4.w = fmaxf(o4.w, 0.f);
            }
            *(float4*)&Y[off] = o4;
        }
    }
}

// ---------------- partial-sum reduce -> per-channel affine ----------------
__global__ void bnred_kernel(const float* __restrict__ psum, const float* __restrict__ psq,
                             const float* __restrict__ g, const float* __restrict__ beta,
                             float* __restrict__ scl, float* __restrict__ shf)
{
    int c = blockIdx.x, t = threadIdx.x;   // 32 threads
    float s = 0.f, q = 0.f;
    for (int p = t; p < 94; p += 32) { s += psum[c*96 + p]; q += psq[c*96 + p]; }
#pragma unroll
    for (int o = 16; o; o >>= 1) {
        s += __shfl_xor_sync(0xffffffffu, s, o);
        q += __shfl_xor_sync(0xffffffffu, q, o);
    }
    if (t == 0) {
        float inv = 1.f / (float)(BB*NPT);
        float m = s * inv;
        float var = q * inv - m*m;
        float rs = rsqrtf(var + EPSBN);
        scl[c] = g[c] * rs;
        shf[c] = beta[c] - m * g[c] * rs;
    }
}

// ---------------- flash attention (unchanged from passing R8 version) ----------------
struct FlashS {
    float Qt[TQ][132];
    float Kt[TI][132];
    float Vs[CCH][TI];
    float Pd[TQ][68];
    float pI[TI][6];
    float alph[TQ];
};

__global__ void __launch_bounds__(512, 1) flash_kernel(
    const float* __restrict__ Qt, const float* __restrict__ Kt,
    const float* __restrict__ V,
    const float* __restrict__ src, const float* __restrict__ tgt,
    float* __restrict__ Op, float* __restrict__ Lp, float* __restrict__ Mm)
{
    extern __shared__ char smem_raw[];
    FlashS& S = *reinterpret_cast<FlashS*>(smem_raw);
    int tid = threadIdx.x;
    int otile = blockIdx.x * TQ;
    int sp = blockIdx.y, b = blockIdx.z;
    int sbase = sp * SPLEN;
    int send  = min(sbase + SPLEN, NPT);

    int og = tid >> 4;       // 0..31
    int tx = tid & 15;
    int o0 = og << 1;
    int cg = tid >> 4;
    int ox = tid & 15;

#pragma unroll
    for (int j = 0; j < 4; j++) {
        int idx = tid + (j << 9);
        int row = idx >> 5, c4 = (idx & 31) << 2;
        int go = otile + row;
        float4 qv = make_float4(0.f,0.f,0.f,0.f);
        if (go < NPT) qv = *(const float4*)&Qt[((size_t)b*NPT + go)*CCH + c4];
        *(float4*)&S.Qt[row][c4] = qv;
    }
    float pO[2][6];
#pragma unroll
    for (int oo = 0; oo < 2; oo++) {
        int go = otile + o0 + oo;
        if (go < NPT) {
#pragma unroll
            for (int e = 0; e < 3; e++) {
                pO[oo][e]   = src[((size_t)b*NPT + go)*3 + e];
                pO[oo][3+e] = tgt[((size_t)b*NPT + go)*3 + e];
            }
        } else {
#pragma unroll
            for (int e = 0; e < 6; e++) pO[oo][e] = 0.f;
        }
    }
    float mr[2] = {NEGBIG, NEGBIG};
    float lr[2] = {0.f, 0.f};
    ull accO[4][4];
#pragma unroll
    for (int i = 0; i < 4; i++)
#pragma unroll
        for (int j = 0; j < 4; j++) accO[i][j] = 0ull;

    const int nch = (send - sbase + TI - 1) / TI;
#pragma unroll 1
    for (int ch = 0; ch < nch; ch++) {
        int ibase = sbase + ch * TI;
        __syncthreads();
#pragma unroll
        for (int j = 0; j < 4; j++) {
            int idx = tid + (j << 9);
            int row = idx >> 5, c4 = (idx & 31) << 2;
            int gi = ibase + row;
            float4 kv = make_float4(0.f,0.f,0.f,0.f);
            if (gi < send) kv = *(const float4*)&Kt[((size_t)b*NPT + gi)*CCH + c4];
            *(float4*)&S.Kt[row][c4] = kv;
        }
#pragma unroll
        for (int j = 0; j < 4; j++) {
            int idx = tid + (j << 9);
            int c = idx >> 4, i4 = (idx & 15) << 2;
            int gi = ibase + i4;
            float4 vv = make_float4(0.f,0.f,0.f,0.f);
            if (gi < send) vv = *(const float4*)&V[((size_t)(b*CCH + c))*NPT + gi];
            *(float4*)&S.Vs[c][i4] = vv;
        }
        if (tid < TI) {
            int gi = ibase + tid;
            if (gi < send) {
#pragma unroll
                for (int e = 0; e < 3; e++) {
                    S.pI[tid][e]   = src[((size_t)b*NPT + gi)*3 + e];
                    S.pI[tid][3+e] = tgt[((size_t)b*NPT + gi)*3 + e];
                }
            } else {
#pragma unroll
                for (int e = 0; e < 6; e++) S.pI[tid][e] = 0.f;
            }
        }
        __syncthreads();

        ull sacc[2][4];
#pragma unroll
        for (int i = 0; i < 2; i++)
#pragma unroll
            for (int j = 0; j < 4; j++) sacc[i][j] = 0ull;
#pragma unroll 4
        for (int cq = 0; cq < CCH; cq += 4) {
            double2 a0 = *(const double2*)&S.Qt[o0][cq];
            double2 a1 = *(const double2*)&S.Qt[o0+1][cq];
            ull a00 = d2u(a0.x), a01 = d2u(a0.y);
            ull a10 = d2u(a1.x), a11 = d2u(a1.y);
#pragma unroll
            for (int ik = 0; ik < 4; ik++) {
                double2 bq = *(const double2*)&S.Kt[tx + (ik << 4)][cq];
                ull b01 = d2u(bq.x), b23 = d2u(bq.y);
                ffma2(sacc[0][ik], a00, b01);
                ffma2(sacc[0][ik], a01, b23);
                ffma2(sacc[1][ik], a10, b01);
                ffma2(sacc[1][ik], a11, b23);
            }
        }

        float sv[2][4];
#pragma unroll
        for (int oo = 0; oo < 2; oo++)
#pragma unroll
            for (int ik = 0; ik < 4; ik++) {
                float2 f = unp(sacc[oo][ik]);
                sv[oo][ik] = f.x + f.y;
            }
#pragma unroll
        for (int ik = 0; ik < 4; ik++) {
            int il = tx + (ik << 4);
            int gi = ibase + il;
            bool valid = gi < send;
            float pi0 = S.pI[il][0], pi1 = S.pI[il][1], pi2 = S.pI[il][2];
            float pi3 = S.pI[il][3], pi4 = S.pI[il][4], pi5 = S.pI[il][5];
#pragma unroll
            for (int oo = 0; oo < 2; oo++) {
                float dx = pO[oo][0] - pi0, dy = pO[oo][1] - pi1, dz = pO[oo][2] - pi2;
                float ds = sqrt_approx(dx*dx + dy*dy + dz*dz);
                dx = pO[oo][3] - pi3; dy = pO[oo][4] - pi4; dz = pO[oo][5] - pi5;
                float dt = sqrt_approx(dx*dx + dy*dy + dz*dz);
                float d = ds - dt;
                float scv = fmaxf(1.f - d*d, 0.f) * ATT_SCALE;
                sv[oo][ik] = valid ? sv[oo][ik] * scv : NEGBIG;
            }
        }
#pragma unroll
        for (int oo = 0; oo < 2; oo++) {
            float mx = fmaxf(fmaxf(sv[oo][0], sv[oo][1]), fmaxf(sv[oo][2], sv[oo][3]));
#pragma unroll
            for (int s = 8; s; s >>= 1) mx = fmaxf(mx, __shfl_xor_sync(0xffffffffu, mx, s, 16));
            float mnew = fmaxf(mr[oo], mx);
            float al = __expf(mr[oo] - mnew);
            mr[oo] = mnew;
            float psum = 0.f;
#pragma unroll
            for (int ik = 0; ik < 4; ik++) {
                float p = __expf(sv[oo][ik] - mnew);
                S.Pd[o0 + oo][tx + (ik << 4)] = p;
                psum += p;
            }
#pragma unroll
            for (int s = 8; s; s >>= 1) psum += __shfl_xor_sync(0xffffffffu, psum, s, 16);
            lr[oo] = lr[oo] * al + psum;
            if (tx == 0) S.alph[o0 + oo] = al;
        }
        __syncthreads();

#pragma unroll
        for (int ok = 0; ok < 4; ok++) {
            float al = S.alph[ox + (ok << 4)];
            ull ad = packdup(al);
#pragma unroll
            for (int cc = 0; cc < 4; cc++) mulf2(accO[cc][ok], ad);
        }
        int c0 = cg << 2;
#pragma unroll 2
        for (int iq = 0; iq < TI; iq += 4) {
            double2 av[4], bv[4];
#pragma unroll
            for (int cc = 0; cc < 4; cc++) av[cc] = *(const double2*)&S.Vs[c0 + cc][iq];
#pragma unroll
            for (int ok = 0; ok < 4; ok++) bv[ok] = *(const double2*)&S.Pd[ox + (ok << 4)][iq];
#pragma unroll
            for (int cc = 0; cc < 4; cc++) {
                ull ax = d2u(av[cc].x), ay = d2u(av[cc].y);
#pragma unroll
                for (int ok = 0; ok < 4; ok++) {
                    ffma2(accO[cc][ok], ax, d2u(bv[ok].x));
                    ffma2(accO[cc][ok], ay, d2u(bv[ok].y));
                }
            }
        }
    }

    int c0 = cg << 2;
#pragma unroll
    for (int cc = 0; cc < 4; cc++)
#pragma unroll
        for (int ok = 0; ok < 4; ok++) {
            float2 f = unp(accO[cc][ok]);
            float val = f.x + f.y;
            int go = otile + ox + (ok << 4);
            if (go < NPT)
                Op[((size_t)((sp*BB + b)*CCH + c0 + cc))*OPAD + go] = val;
        }
    if (tx == 0) {
#pragma unroll
        for (int oo = 0; oo < 2; oo++) {
            int go = otile + o0 + oo;
            if (go < NPT) {
                Mm[(sp*BB + b)*OPAD + go] = mr[oo];
                Lp[(sp*BB + b)*OPAD + go] = lr[oo];
            }
        }
    }
}

// ---------------- per-point split combine weights ----------------
__global__ void wcomb_kernel(const float* __restrict__ Mm, const float* __restrict__ Lp,
                             float* __restrict__ wc)
{
    int t = blockIdx.x * blockDim.x + threadIdx.x;
    if (t >= BB*NPT) return;
    int b = t / NPT, o = t - b*NPT;
    float mv[ISPLIT], lv[ISPLIT];
#pragma unroll
    for (int s = 0; s < ISPLIT; s++) {
        mv[s] = Mm[(s*BB + b)*OPAD + o];
        lv[s] = Lp[(s*BB + b)*OPAD + o];
    }
    float Mx = fmaxf(fmaxf(mv[0], mv[1]), mv[2]);
    float w0 = __expf(mv[0] - Mx), w1 = __expf(mv[1] - Mx), w2 = __expf(mv[2] - Mx);
    float inv = 1.f / (lv[0]*w0 + lv[1]*w1 + lv[2]*w2);
    wc[(0*BB + b)*OPAD + o] = w0 * inv;
    wc[(1*BB + b)*OPAD + o] = w1 * inv;
    wc[(2*BB + b)*OPAD + o] = w2 * inv;
}

// ---------------- fused head: norm + c1 + c2 + c3 ----------------
struct HeadS {
    float xt[CCH][68];
    float cw1[32][128];
    float cw2[32][32];
    float cw3[32];
    float b1[32], b2[32];
    float ph1[64][33];
    float ph2[64][33];
    float sinv[64];
};

__global__ void __launch_bounds__(256) head_kernel(const float* __restrict__ X,
        const float* __restrict__ c1W, const float* __restrict__ c1b,
        const float* __restrict__ c2W, const float* __restrict__ c2b,
        const float* __restrict__ c3W, const float* __restrict__ c3b,
        float* __restrict__ out)
{
    extern __shared__ char sraw[];
    HeadS& S = *reinterpret_cast<HeadS*>(sraw);
    int tid = threadIdx.x;
    int n0 = blockIdx.x << 6, b = blockIdx.y;

    for (int i = tid; i < 32*128; i += 256) S.cw1[i >> 7][i & 127] = c1W[i];
    for (int i = tid; i < 32*32;  i += 256) S.cw2[i >> 5][i & 31]  = c2W[i];
    if (tid < 32) { S.cw3[tid] = c3W[tid]; S.b1[tid] = c1b[tid]; S.b2[tid] = c2b[tid]; }
    for (int t = tid; t < CCH*16; t += 256) {
        int row = t >> 4, j4 = (t & 15) << 2;
        float4 v = make_float4(0.f,0.f,0.f,0.f);
        if (n0 + j4 < NPT) v = *(const float4*)&X[((size_t)(b*CCH + row))*NPT + n0 + j4];
        *(float4*)&S.xt[row][j4] = v;
    }
    __syncthreads();

    int p = tid >> 2, qd = tid & 3;
    // norm
    float ss = 0.f;
    for (int c = qd*32; c < qd*32 + 32; c++) { float v = S.xt[c][p]; ss += v*v; }
    ss += __shfl_xor_sync(0xffffffffu, ss, 1, 4);
    ss += __shfl_xor_sync(0xffffffffu, ss, 2, 4);
    if (qd == 0) S.sinv[p] = 1.f / fmaxf(sqrtf(ss), 1e-12f);

    // h1 = relu(c1 x)
#pragma unroll
    for (int jj = 0; jj < 8; jj++) {
        int j = qd*8 + jj;
        float a = S.b1[j];
        for (int c = 0; c < CCH; c++) a += S.cw1[j][c] * S.xt[c][p];
        S.ph1[p][j] = fmaxf(a, 0.f);
    }
    __syncthreads();
    // h2 = relu(c2 h1)
#pragma unroll
    for (int jj = 0; jj < 8; jj++) {
        int j = qd*8 + jj;
        float a = S.b2[j];
        for (int c = 0; c < 32; c++) a += S.cw2[j][c] * S.ph1[p][c];
        S.ph2[p][j] = fmaxf(a, 0.f);
    }
    __syncthreads();
    if (qd == 0) {
        float a = c3b[0];
        for (int c = 0; c < 32; c++) a += S.cw3[c] * S.ph2[p][c];
        int n = n0 + p;
        if (n < NPT) out[b*NPT + n] = a;
    }
    // normed features
    float* dst = out + BB*NPT;
    for (int t = tid; t < CCH*16; t += 256) {
        int row = t >> 4, j4 = (t & 15) << 2;
#pragma unroll
        for (int e = 0; e < 4; e++) {
            int n = n0 + j4 + e;
            if (n < NPT)
                dst[((size_t)(b*CCH + row))*NPT + n] = S.xt[row][j4 + e] * S.sinv[j4 + e];
        }
    }
}

// ======================= host launcher =======================
extern "C" void kernel_launch(void* const* d_in, const int* in_sizes, int n_in,
                              void* d_out, int out_size)
{
    const float* corr    = (const float*)d_in[0];
    const float* src     = (const float*)d_in[1];
    const float* tgt     = (const float*)d_in[2];
    const float* iW      = (const float*)d_in[3];
    const float* ib      = (const float*)d_in[4];
    const float* pcnW    = (const float*)d_in[5];
    const float* pcnb    = (const float*)d_in[6];
    const float* pcng    = (const float*)d_in[7];
    const float* pcnbeta = (const float*)d_in[8];
    const float* qW  = (const float*)d_in[9];  const float* qb  = (const float*)d_in[10];
    const float* kW  = (const float*)d_in[11]; const float* kb  = (const float*)d_in[12];
    const float* vW  = (const float*)d_in[13]; const float* vb  = (const float*)d_in[14];
    const float* m1W = (const float*)d_in[15]; const float* m1b = (const float*)d_in[16];
    const float* m1g = (const float*)d_in[17]; const float* m1beta = (const float*)d_in[18];
    const float* m2W = (const float*)d_in[19]; const float* m2b = (const float*)d_in[20];
    const float* m2g = (const float*)d_in[21]; const float* m2beta = (const float*)d_in[22];
    const float* m3W = (const float*)d_in[23]; const float* m3b = (const float*)d_in[24];
    const float* c1W = (const float*)d_in[25]; const float* c1b = (const float*)d_in[26];
    const float* c2W = (const float*)d_in[27]; const float* c2b = (const float*)d_in[28];
    const float* c3W = (const float*)d_in[29]; const float* c3b = (const float*)d_in[30];
    float* out = (float*)d_out;

    float *x, *y, *v, *m, *h, *qt, *kt, *Op, *Lp, *Mm, *wc, *ps, *pq;
    float *scl, *shf, *scl1, *shf1, *scl2, *shf2;
    cudaGetSymbolAddress((void**)&x,  g_x);
    cudaGetSymbolAddress((void**)&y,  g_y);
    cudaGetSymbolAddress((void**)&v,  g_v);
    cudaGetSymbolAddress((void**)&m,  g_m);
    cudaGetSymbolAddress((void**)&h,  g_h);
    cudaGetSymbolAddress((void**)&qt, g_qt);
    cudaGetSymbolAddress((void**)&kt, g_kt);
    cudaGetSymbolAddress((void**)&Op, g_Op);
    cudaGetSymbolAddress((void**)&Lp, g_Lp);
    cudaGetSymbolAddress((void**)&Mm, g_Mm);
    cudaGetSymbolAddress((void**)&wc, g_wc);
    cudaGetSymbolAddress((void**)&ps, g_ps);
    cudaGetSymbolAddress((void**)&pq, g_pq);
    cudaGetSymbolAddress((void**)&scl,  g_scl);  cudaGetSymbolAddress((void**)&shf,  g_shf);
    cudaGetSymbolAddress((void**)&scl1, g_scl1); cudaGetSymbolAddress((void**)&shf1, g_shf1);
    cudaGetSymbolAddress((void**)&scl2, g_scl2); cudaGetSymbolAddress((void**)&shf2, g_shf2);

    const int nT64 = (NPT + 63) / 64;        // 47
    const int smemFlash = (int)sizeof(FlashS);
    const int smemHead  = (int)sizeof(HeadS);
    cudaFuncSetAttribute(flash_kernel, cudaFuncAttributeMaxDynamicSharedMemorySize, smemFlash);
    cudaFuncSetAttribute(head_kernel,  cudaFuncAttributeMaxDynamicSharedMemorySize, smemHead);

    dim3 blk(256);
    init_conv_kernel<<<(BB*NPT + 127)/128, 128>>>(corr, iW, ib, x);

    for (int l = 0; l < LL; l++) {
        // PointCN conv (pre-BN output y) + stats partials
        conv_kernel<0,false,0,false,true><<<dim3(nT64,2,BB), blk>>>(
            x, pcnW + (size_t)l*CCH*CCH, pcnb + l*CCH,
            nullptr, nullptr, nullptr, nullptr, nullptr, nullptr,
            y, ps, pq, CCH, CCH);
        bnred_kernel<<<CCH, 32>>>(ps, pq, pcng + l*CCH, pcnbeta + l*CCH, scl, shf);

        // Q, K (transposed out), V — pcn affine+relu fused on load
        conv_kernel<1,false,0,true,false><<<dim3(nT64,2,BB), blk>>>(
            y, qW + (size_t)l*CCH*CCH, qb + l*CCH,
            scl, shf, nullptr, nullptr, nullptr, nullptr,
            qt, nullptr, nullptr, CCH, CCH);
        conv_kernel<1,false,0,true,false><<<dim3(nT64,2,BB), blk>>>(
            y, kW + (size_t)l*CCH*CCH, kb + l*CCH,
            scl, shf, nullptr, nullptr, nullptr, nullptr,
            kt, nullptr, nullptr, CCH, CCH);
        conv_kernel<1,false,0,false,false><<<dim3(nT64,2,BB), blk>>>(
            y, vW + (size_t)l*CCH*CCH, vb + l*CCH,
            scl, shf, nullptr, nullptr, nullptr, nullptr,
            v, nullptr, nullptr, CCH, CCH);

        // flash attention + combine weights
        flash_kernel<<<dim3(nT64, ISPLIT, BB), 512, smemFlash>>>(qt, kt, v, src, tgt, Op, Lp, Mm);
        wcomb_kernel<<<(BB*NPT + 255)/256, 256>>>(Mm, Lp, wc);

        // m1: merge partials on load, stats out
        conv_kernel<3,false,0,false,true><<<dim3(nT64,1,BB), blk>>>(
            Op, m1W + (size_t)l*CH*CCH, m1b + l*CH,
            nullptr, nullptr, nullptr, nullptr, nullptr, wc,
            m, ps, pq, CCH, CH);
        bnred_kernel<<<CH, 32>>>(ps, pq, m1g + l*CH, m1beta + l*CH, scl1, shf1);

        // m2: affine1 on load, stats out
        conv_kernel<1,false,0,false,true><<<dim3(nT64,1,BB), blk>>>(
            m, m2W + (size_t)l*CH*CH, m2b + l*CH,
            scl1, shf1, nullptr, nullptr, nullptr, nullptr,
            h, ps, pq, CH, CH);
        bnred_kernel<<<CH, 32>>>(ps, pq, m2g + l*CH, m2beta + l*CH, scl2, shf2);

        // m3: affine2 on load, residual = relu(affine_pcn(y)), out -> x
        conv_kernel<1,false,2,false,false><<<dim3(nT64,2,BB), blk>>>(
            h, m3W + (size_t)l*CCH*CH, m3b + l*CCH,
            scl2, shf2, y, scl, shf, nullptr,
            x, nullptr, nullptr, CH, CCH);
    }

    // fused head: norm + c1 + c2 + c3
    head_kernel<<<dim3(nT64, BB), 256, smemHead>>>(x, c1W, c1b, c2W, c2b, c3W, c3b, out);
}

// round 11
// speedup vs baseline: 2.0343x; 1.1679x over previous
#include <cuda_runtime.h>
#include <math.h>

#define NPT 3000
#define BB 2
#define CCH 128
#define CH 64
#define LL 6
#define EPSBN 1e-5f
#define ATT_SCALE 0.08838834764831845f  // 1/sqrt(128)

#define TQ 64
#define TI 128
#define ISPLIT 3
#define SPLEN 1000
#define OPAD 3008
#define NEGBIG -1e30f

typedef unsigned long long ull;

__device__ __forceinline__ void ffma2(ull &d, ull a, ull b) {
    asm("fma.rn.f32x2 %0, %1, %2, %0;" : "+l"(d) : "l"(a), "l"(b));
}
__device__ __forceinline__ void mulf2(ull &d, ull f) {
    asm("mul.rn.f32x2 %0, %0, %1;" : "+l"(d) : "l"(f));
}
__device__ __forceinline__ float2 unp(ull v) {
    unsigned lo, hi;
    asm("mov.b64 {%0,%1}, %2;" : "=r"(lo), "=r"(hi) : "l"(v));
    return make_float2(__uint_as_float(lo), __uint_as_float(hi));
}
__device__ __forceinline__ ull packdup(float x) {
    ull r; unsigned u = __float_as_uint(x);
    asm("mov.b64 %0, {%1, %1};" : "=l"(r) : "r"(u));
    return r;
}
__device__ __forceinline__ ull d2u(double d) { return __double_as_longlong(d); }
__device__ __forceinline__ float sqrt_approx(float x) {
    float r; asm("sqrt.approx.f32 %0, %1;" : "=f"(r) : "f"(x)); return r;
}

// ---------------- device scratch ----------------
__device__ float g_x[BB*CCH*NPT];
__device__ float g_y[BB*CCH*NPT];
__device__ float g_v[BB*CCH*NPT];
__device__ float g_m[BB*CCH*NPT];
__device__ float g_h[BB*CCH*NPT];
__device__ float g_qt[(size_t)BB*NPT*CCH];
__device__ float g_kt[(size_t)BB*NPT*CCH];
__device__ float g_Op[(size_t)ISPLIT*BB*CCH*OPAD];
__device__ float g_Lp[ISPLIT*BB*OPAD];
__device__ float g_Mm[ISPLIT*BB*OPAD];
__device__ float g_ps[CCH*96], g_pq[CCH*96];
__device__ float g_scl[CCH],  g_shf[CCH];
__device__ float g_scl1[CCH], g_shf1[CCH];
__device__ float g_scl2[CCH], g_shf2[CCH];

// ---------------- init embedding ----------------
__global__ void init_conv_kernel(const float* __restrict__ corr, const float* __restrict__ W,
                                 const float* __restrict__ bias, float* __restrict__ X)
{
    __shared__ float Ws[CCH*6];
    __shared__ float bs[CCH];
    int tid = threadIdx.x;
    for (int i = tid; i < CCH*6; i += blockDim.x) Ws[i] = W[i];
    for (int i = tid; i < CCH;   i += blockDim.x) bs[i] = bias[i];
    __syncthreads();
    int idx = blockIdx.x * blockDim.x + tid;
    if (idx >= BB*NPT) return;
    int b = idx / NPT, n = idx - b*NPT;
    float cp[6];
#pragma unroll
    for (int j = 0; j < 6; j++) cp[j] = corr[(size_t)idx*6 + j];
    for (int co = 0; co < CCH; co++) {
        float a = bs[co];
#pragma unroll
        for (int j = 0; j < 6; j++) a += Ws[co*6 + j] * cp[j];
        X[((size_t)b*CCH + co)*NPT + n] = a;
    }
}

// ---------------- pointwise conv (pcn/m1/m2/m3) ----------------
// INMODE: 0 plain, 1 relu(scl*x+shf) on input, 3 weighted 3-way Op merge (weights from Mm/Lp)
// RES:    0 none, 2 residual r -> relu(rscl*r+rshf)   (rscl/rshf double as Mm/Lp for INMODE 3)
// STATS:  emit per-(c, block) partial sum/sumsq
template<int INMODE, int RES, bool STATS>
__global__ void __launch_bounds__(256) conv_kernel(const float* __restrict__ X,
        const float* __restrict__ W, const float* __restrict__ bias,
        const float* __restrict__ scl, const float* __restrict__ shf,
        const float* __restrict__ R, const float* __restrict__ rscl,
        const float* __restrict__ rshf,
        float* __restrict__ Y, float* __restrict__ psum, float* __restrict__ psq,
        int Cin, int Cout)
{
    __shared__ float Ws[16][128];   // co duplicated
    __shared__ float Xs[16][64];
    __shared__ float sA[CCH], sB[CCH];
    __shared__ float swc[ISPLIT][64];
    int tid = threadIdx.x;
    int b = blockIdx.z, c0 = blockIdx.y << 6, n0 = blockIdx.x << 6;
    if (INMODE == 1) {
        if (tid < Cin) { sA[tid] = scl[tid]; sB[tid] = shf[tid]; }
    }
    if (INMODE == 3) {
        if (tid < 64) {
            int n = n0 + tid;
            float w0 = 0.f, w1 = 0.f, w2 = 0.f;
            if (n < NPT) {
                float m0 = rscl[(0*BB + b)*OPAD + n];
                float m1v = rscl[(1*BB + b)*OPAD + n];
                float m2v = rscl[(2*BB + b)*OPAD + n];
                float l0 = rshf[(0*BB + b)*OPAD + n];
                float l1 = rshf[(1*BB + b)*OPAD + n];
                float l2 = rshf[(2*BB + b)*OPAD + n];
                float Mx = fmaxf(fmaxf(m0, m1v), m2v);
                w0 = __expf(m0 - Mx); w1 = __expf(m1v - Mx); w2 = __expf(m2v - Mx);
                float inv = 1.f / (l0*w0 + l1*w1 + l2*w2);
                w0 *= inv; w1 *= inv; w2 *= inv;
            }
            swc[0][tid] = w0; swc[1][tid] = w1; swc[2][tid] = w2;
        }
    }
    int ty = tid >> 4, tx = tid & 15;
    ull acc[4][2];
#pragma unroll
    for (int i = 0; i < 4; i++) { acc[i][0] = 0ull; acc[i][1] = 0ull; }

#pragma unroll 1
    for (int kt = 0; kt < Cin; kt += 16) {
        __syncthreads();
        {
            int m = tid >> 2, kk4 = (tid & 3) << 2;
            float4 w = make_float4(0.f,0.f,0.f,0.f);
            if (c0 + m < Cout) w = *(const float4*)&W[(size_t)(c0 + m)*Cin + kt + kk4];
            Ws[kk4][2*m] = w.x;   Ws[kk4][2*m+1] = w.x;
            Ws[kk4+1][2*m] = w.y; Ws[kk4+1][2*m+1] = w.y;
            Ws[kk4+2][2*m] = w.z; Ws[kk4+2][2*m+1] = w.z;
            Ws[kk4+3][2*m] = w.w; Ws[kk4+3][2*m+1] = w.w;
        }
        {
            int kk = tid >> 4, j4 = (tid & 15) << 2;
            int ci = kt + kk;
            float4 v = make_float4(0.f,0.f,0.f,0.f);
            if (INMODE == 3) {
                const size_t sstr = (size_t)BB*CCH*OPAD;
                const float* base = X + ((size_t)(b*CCH + ci))*OPAD + n0 + j4;
                float4 a0 = *(const float4*)&base[0];
                float4 a1 = *(const float4*)&base[sstr];
                float4 a2 = *(const float4*)&base[2*sstr];
                v.x = a0.x*swc[0][j4]   + a1.x*swc[1][j4]   + a2.x*swc[2][j4];
                v.y = a0.y*swc[0][j4+1] + a1.y*swc[1][j4+1] + a2.y*swc[2][j4+1];
                v.z = a0.z*swc[0][j4+2] + a1.z*swc[1][j4+2] + a2.z*swc[2][j4+2];
                v.w = a0.w*swc[0][j4+3] + a1.w*swc[1][j4+3] + a2.w*swc[2][j4+3];
            } else if (n0 + j4 < NPT) {
                v = *(const float4*)&X[((size_t)(b*Cin + ci))*NPT + n0 + j4];
                if (INMODE == 1) {
                    float sa = sA[ci], sb = sB[ci];
                    v.x = fmaxf(fmaf(sa, v.x, sb), 0.f);
                    v.y = fmaxf(fmaf(sa, v.y, sb), 0.f);
                    v.z = fmaxf(fmaf(sa, v.z, sb), 0.f);
                    v.w = fmaxf(fmaf(sa, v.w, sb), 0.f);
                }
            }
            *(float4*)&Xs[kk][j4] = v;
        }
        __syncthreads();
#pragma unroll
        for (int kk = 0; kk < 16; kk++) {
            const double2* wp = (const double2*)&Ws[kk][ty << 3];
            double2 w0 = wp[0], w1 = wp[1];
            ull a[4] = {d2u(w0.x), d2u(w0.y), d2u(w1.x), d2u(w1.y)};
            const double2* xp = (const double2*)&Xs[kk][tx << 2];
            double2 x0 = xp[0];
            ull b0 = d2u(x0.x), b1 = d2u(x0.y);
#pragma unroll
            for (int mi = 0; mi < 4; mi++) {
                ffma2(acc[mi][0], a[mi], b0);
                ffma2(acc[mi][1], a[mi], b1);
            }
        }
    }

    int n = n0 + (tx << 2);
    bool nok = (n < NPT);
    float vals[4][4];
#pragma unroll
    for (int mi = 0; mi < 4; mi++) {
        int co = c0 + (ty << 2) + mi;
        float bv = (co < Cout) ? bias[co] : 0.f;
        float2 f0 = unp(acc[mi][0]), f1 = unp(acc[mi][1]);
        vals[mi][0] = f0.x + bv; vals[mi][1] = f0.y + bv;
        vals[mi][2] = f1.x + bv; vals[mi][3] = f1.y + bv;
    }

    if (STATS) {
#pragma unroll
        for (int mi = 0; mi < 4; mi++) {
            float s = 0.f, sq = 0.f;
            if (nok)
#pragma unroll
                for (int j = 0; j < 4; j++) { s += vals[mi][j]; sq += vals[mi][j]*vals[mi][j]; }
#pragma unroll
            for (int o = 8; o; o >>= 1) {
                s  += __shfl_xor_sync(0xffffffffu, s,  o, 16);
                sq += __shfl_xor_sync(0xffffffffu, sq, o, 16);
            }
            if (tx == 0) {
                int co = c0 + (ty << 2) + mi;
                if (co < Cout) {
                    int p = b*47 + blockIdx.x;
                    psum[co*96 + p] = s;
                    psq[co*96 + p]  = sq;
                }
            }
        }
    }

    if (!nok) return;
#pragma unroll
    for (int mi = 0; mi < 4; mi++) {
        int co = c0 + (ty << 2) + mi;
        if (co >= Cout) continue;
        float4 o4 = make_float4(vals[mi][0], vals[mi][1], vals[mi][2], vals[mi][3]);
        size_t off = ((size_t)(b*Cout + co))*NPT + n;
        if (RES == 2) {
            float4 r = *(const float4*)&R[off];
            float ra = rscl[co], rb = rshf[co];
            o4.x += fmaxf(fmaf(ra, r.x, rb), 0.f);
            o4.y += fmaxf(fmaf(ra, r.y, rb), 0.f);
            o4.z += fmaxf(fmaf(ra, r.z, rb), 0.f);
            o4.w += fmaxf(fmaf(ra, r.w, rb), 0.f);
        }
        *(float4*)&Y[off] = o4;
    }
}

// ---------------- fused q/k/v conv (one launch, 564 blocks) ----------------
__global__ void __launch_bounds__(256) qkv_kernel(const float* __restrict__ X,
        const float* __restrict__ qW, const float* __restrict__ kW, const float* __restrict__ vW,
        const float* __restrict__ qb, const float* __restrict__ kb, const float* __restrict__ vb,
        const float* __restrict__ scl, const float* __restrict__ shf,
        float* __restrict__ qt, float* __restrict__ kt, float* __restrict__ v)
{
    __shared__ float Ws[16][128];
    __shared__ float Xs[16][64];
    __shared__ float sA[CCH], sB[CCH];
    int tid = threadIdx.x;
    int sel = blockIdx.y >> 1;
    const float* W    = (sel == 0) ? qW : (sel == 1) ? kW : vW;
    const float* bias = (sel == 0) ? qb : (sel == 1) ? kb : vb;
    int b = blockIdx.z, c0 = (blockIdx.y & 1) << 6, n0 = blockIdx.x << 6;
    if (tid < CCH) { sA[tid] = scl[tid]; sB[tid] = shf[tid]; }
    int ty = tid >> 4, tx = tid & 15;
    ull acc[4][2];
#pragma unroll
    for (int i = 0; i < 4; i++) { acc[i][0] = 0ull; acc[i][1] = 0ull; }

#pragma unroll 1
    for (int kt0 = 0; kt0 < CCH; kt0 += 16) {
        __syncthreads();
        {
            int m = tid >> 2, kk4 = (tid & 3) << 2;
            float4 w = *(const float4*)&W[(size_t)(c0 + m)*CCH + kt0 + kk4];
            Ws[kk4][2*m] = w.x;   Ws[kk4][2*m+1] = w.x;
            Ws[kk4+1][2*m] = w.y; Ws[kk4+1][2*m+1] = w.y;
            Ws[kk4+2][2*m] = w.z; Ws[kk4+2][2*m+1] = w.z;
            Ws[kk4+3][2*m] = w.w; Ws[kk4+3][2*m+1] = w.w;
        }
        {
            int kk = tid >> 4, j4 = (tid & 15) << 2;
            int ci = kt0 + kk;
            float4 vv = make_float4(0.f,0.f,0.f,0.f);
            if (n0 + j4 < NPT) {
                vv = *(const float4*)&X[((size_t)(b*CCH + ci))*NPT + n0 + j4];
                float sa = sA[ci], sb = sB[ci];
                vv.x = fmaxf(fmaf(sa, vv.x, sb), 0.f);
                vv.y = fmaxf(fmaf(sa, vv.y, sb), 0.f);
                vv.z = fmaxf(fmaf(sa, vv.z, sb), 0.f);
                vv.w = fmaxf(fmaf(sa, vv.w, sb), 0.f);
            }
            *(float4*)&Xs[kk][j4] = vv;
        }
        __syncthreads();
#pragma unroll
        for (int kk = 0; kk < 16; kk++) {
            const double2* wp = (const double2*)&Ws[kk][ty << 3];
            double2 w0 = wp[0], w1 = wp[1];
            ull a[4] = {d2u(w0.x), d2u(w0.y), d2u(w1.x), d2u(w1.y)};
            const double2* xp = (const double2*)&Xs[kk][tx << 2];
            double2 x0 = xp[0];
            ull b0 = d2u(x0.x), b1 = d2u(x0.y);
#pragma unroll
            for (int mi = 0; mi < 4; mi++) {
                ffma2(acc[mi][0], a[mi], b0);
                ffma2(acc[mi][1], a[mi], b1);
            }
        }
    }

    int n = n0 + (tx << 2);
    if (n >= NPT) return;
    float vals[4][4];
#pragma unroll
    for (int mi = 0; mi < 4; mi++) {
        int co = c0 + (ty << 2) + mi;
        float bv = bias[co];
        float2 f0 = unp(acc[mi][0]), f1 = unp(acc[mi][1]);
        vals[mi][0] = f0.x + bv; vals[mi][1] = f0.y + bv;
        vals[mi][2] = f1.x + bv; vals[mi][3] = f1.y + bv;
    }
    if (sel < 2) {
        float* base = ((sel == 0) ? qt : kt) + (size_t)b*NPT*CCH;
        int cb = c0 + (ty << 2);
#pragma unroll
        for (int j = 0; j < 4; j++) {
            if (n + j >= NPT) continue;
            *(float4*)&base[(size_t)(n + j)*CCH + cb] =
                make_float4(vals[0][j], vals[1][j], vals[2][j], vals[3][j]);
        }
    } else {
#pragma unroll
        for (int mi = 0; mi < 4; mi++) {
            int co = c0 + (ty << 2) + mi;
            *(float4*)&v[((size_t)(b*CCH + co))*NPT + n] =
                make_float4(vals[mi][0], vals[mi][1], vals[mi][2], vals[mi][3]);
        }
    }
}

// ---------------- partial-sum reduce -> per-channel affine ----------------
__global__ void bnred_kernel(const float* __restrict__ psum, const float* __restrict__ psq,
                             const float* __restrict__ g, const float* __restrict__ beta,
                             float* __restrict__ scl, float* __restrict__ shf)
{
    int c = blockIdx.x, t = threadIdx.x;
    float s = 0.f, q = 0.f;
    for (int p = t; p < 94; p += 32) { s += psum[c*96 + p]; q += psq[c*96 + p]; }
#pragma unroll
    for (int o = 16; o; o >>= 1) {
        s += __shfl_xor_sync(0xffffffffu, s, o);
        q += __shfl_xor_sync(0xffffffffu, q, o);
    }
    if (t == 0) {
        float inv = 1.f / (float)(BB*NPT);
        float m = s * inv;
        float var = q * inv - m*m;
        float rs = rsqrtf(var + EPSBN);
        scl[c] = g[c] * rs;
        shf[c] = beta[c] - m * g[c] * rs;
    }
}

// ---------------- flash attention (TI=128, warp-uniform broadcast operands) ----------------
struct FlashS {
    float Qt[TQ][132];      // [o][c]
    float KV[CCH*132];      // K chunk: [i][132] (TI rows) ; then V chunk: [c][132]
    float Pd[TQ][132];      // [o][i]
    float pOs[TQ][6];
    float pI[TI][6];
    float alph[TQ];
};

__global__ void __launch_bounds__(512, 1) flash_kernel(
    const float* __restrict__ Qt, const float* __restrict__ Kt,
    const float* __restrict__ V,
    const float* __restrict__ src, const float* __restrict__ tgt,
    float* __restrict__ Op, float* __restrict__ Lp, float* __restrict__ Mm)
{
    extern __shared__ char smem_raw[];
    FlashS& S = *reinterpret_cast<FlashS*>(smem_raw);
    int tid = threadIdx.x;
    int otile = blockIdx.x * TQ;
    int sp = blockIdx.y, b = blockIdx.z;
    int sbase = sp * SPLEN;
    int send  = min(sbase + SPLEN, NPT);
    int warp = tid >> 5, lane = tid & 31;
    int o0 = warp << 2;      // S-phase: warp owns o rows o0..o0+3
    int c0 = warp << 3;      // AV-phase: warp owns c rows c0..c0+7

    // ---- prologue ----
#pragma unroll
    for (int j = 0; j < 4; j++) {
        int idx = tid + (j << 9);
        int row = idx >> 5, c4 = (idx & 31) << 2;
        int go = otile + row;
        float4 qv = make_float4(0.f,0.f,0.f,0.f);
        if (go < NPT) qv = *(const float4*)&Qt[((size_t)b*NPT + go)*CCH + c4];
        *(float4*)&S.Qt[row][c4] = qv;
    }
    if (tid < TQ) {
        int go = otile + tid;
        if (go < NPT) {
#pragma unroll
            for (int e = 0; e < 3; e++) {
                S.pOs[tid][e]   = src[((size_t)b*NPT + go)*3 + e];
                S.pOs[tid][3+e] = tgt[((size_t)b*NPT + go)*3 + e];
            }
        } else {
#pragma unroll
            for (int e = 0; e < 6; e++) S.pOs[tid][e] = 0.f;
        }
    }
    float mr[4] = {NEGBIG, NEGBIG, NEGBIG, NEGBIG};
    float lr[4] = {0.f, 0.f, 0.f, 0.f};
    ull accO[8][2];
#pragma unroll
    for (int i = 0; i < 8; i++) { accO[i][0] = 0ull; accO[i][1] = 0ull; }

    const int nch = (send - sbase + TI - 1) / TI;
#pragma unroll 1
    for (int ch = 0; ch < nch; ch++) {
        int ibase = sbase + ch * TI;
        __syncthreads();
        // K chunk as [i][132]
#pragma unroll
        for (int j = 0; j < 8; j++) {
            int idx = tid + (j << 9);
            int row = idx >> 5, c4 = (idx & 31) << 2;
            int gi = ibase + row;
            float4 kv = make_float4(0.f,0.f,0.f,0.f);
            if (gi < send) kv = *(const float4*)&Kt[((size_t)b*NPT + gi)*CCH + c4];
            *(float4*)&S.KV[row*132 + c4] = kv;
        }
        if (tid < TI) {
            int gi = ibase + tid;
            if (gi < send) {
#pragma unroll
                for (int e = 0; e < 3; e++) {
                    S.pI[tid][e]   = src[((size_t)b*NPT + gi)*3 + e];
                    S.pI[tid][3+e] = tgt[((size_t)b*NPT + gi)*3 + e];
                }
            } else {
#pragma unroll
                for (int e = 0; e < 6; e++) S.pI[tid][e] = 0.f;
            }
        }
        __syncthreads();

        // ---- S-phase: 4o x 4i per thread; Q broadcast, K conflict-free ----
        ull sacc[4][4];
#pragma unroll
        for (int r = 0; r < 4; r++)
#pragma unroll
            for (int s = 0; s < 4; s++) sacc[r][s] = 0ull;
#pragma unroll 4
        for (int cq = 0; cq < CCH; cq += 4) {
            double2 qv[4], kv[4];
#pragma unroll
            for (int r = 0; r < 4; r++) qv[r] = *(const double2*)&S.Qt[o0 + r][cq];
#pragma unroll
            for (int s = 0; s < 4; s++) kv[s] = *(const double2*)&S.KV[(lane + (s << 5))*132 + cq];
#pragma unroll
            for (int r = 0; r < 4; r++) {
                ull ax = d2u(qv[r].x), ay = d2u(qv[r].y);
#pragma unroll
                for (int s = 0; s < 4; s++) {
                    ffma2(sacc[r][s], ax, d2u(kv[s].x));
                    ffma2(sacc[r][s], ay, d2u(kv[s].y));
                }
            }
        }

        // ---- softmax epilogue ----
        float sv[4][4];
#pragma unroll
        for (int r = 0; r < 4; r++)
#pragma unroll
            for (int s = 0; s < 4; s++) {
                float2 f = unp(sacc[r][s]);
                sv[r][s] = f.x + f.y;
            }
#pragma unroll
        for (int s = 0; s < 4; s++) {
            int il = lane + (s << 5);
            bool valid = (ibase + il) < send;
            float pi0 = S.pI[il][0], pi1 = S.pI[il][1], pi2 = S.pI[il][2];
            float pi3 = S.pI[il][3], pi4 = S.pI[il][4], pi5 = S.pI[il][5];
#pragma unroll
            for (int r = 0; r < 4; r++) {
                float dx = S.pOs[o0+r][0] - pi0, dy = S.pOs[o0+r][1] - pi1, dz = S.pOs[o0+r][2] - pi2;
                float ds = sqrt_approx(dx*dx + dy*dy + dz*dz);
                dx = S.pOs[o0+r][3] - pi3; dy = S.pOs[o0+r][4] - pi4; dz = S.pOs[o0+r][5] - pi5;
                float dt = sqrt_approx(dx*dx + dy*dy + dz*dz);
                float d = ds - dt;
                float scv = fmaxf(1.f - d*d, 0.f) * ATT_SCALE;
                sv[r][s] = valid ? sv[r][s] * scv : NEGBIG;
            }
        }
#pragma unroll
        for (int r = 0; r < 4; r++) {
            float mx = fmaxf(fmaxf(sv[r][0], sv[r][1]), fmaxf(sv[r][2], sv[r][3]));
#pragma unroll
            for (int s = 16; s; s >>= 1) mx = fmaxf(mx, __shfl_xor_sync(0xffffffffu, mx, s));
            float mnew = fmaxf(mr[r], mx);
            float al = __expf(mr[r] - mnew);
            mr[r] = mnew;
            float psum = 0.f;
#pragma unroll
            for (int s = 0; s < 4; s++) {
                float p = __expf(sv[r][s] - mnew);
                S.Pd[o0 + r][lane + (s << 5)] = p;
                psum += p;
            }
#pragma unroll
            for (int s = 16; s; s >>= 1) psum += __shfl_xor_sync(0xffffffffu, psum, s);
            lr[r] = lr[r] * al + psum;
            if (lane == 0) S.alph[o0 + r] = al;
        }
        __syncthreads();

        // V chunk overwrites KV as [c][132]
#pragma unroll
        for (int j = 0; j < 8; j++) {
            int idx = tid + (j << 9);
            int row = idx >> 5, i4 = (idx & 31) << 2;
            int gi = ibase + i4;
            float4 vv = make_float4(0.f,0.f,0.f,0.f);
            if (gi < send) vv = *(const float4*)&V[((size_t)(b*CCH + row))*NPT + gi];
            *(float4*)&S.KV[row*132 + i4] = vv;
        }
        __syncthreads();

        // ---- AV: 8c x 2o per thread; V broadcast, Pd conflict-free ----
        {
            ull ad0 = packdup(S.alph[lane]);
            ull ad1 = packdup(S.alph[lane + 32]);
#pragma unroll
            for (int cc = 0; cc < 8; cc++) { mulf2(accO[cc][0], ad0); mulf2(accO[cc][1], ad1); }
        }
#pragma unroll 2
        for (int iq = 0; iq < TI; iq += 4) {
            double2 b0 = *(const double2*)&S.Pd[lane][iq];
            double2 b1 = *(const double2*)&S.Pd[lane + 32][iq];
            ull b0x = d2u(b0.x), b0y = d2u(b0.y), b1x = d2u(b1.x), b1y = d2u(b1.y);
#pragma unroll
            for (int cc = 0; cc < 8; cc++) {
                double2 av = *(const double2*)&S.KV[(c0 + cc)*132 + iq];
                ull ax = d2u(av.x), ay = d2u(av.y);
                ffma2(accO[cc][0], ax, b0x);
                ffma2(accO[cc][0], ay, b0y);
                ffma2(accO[cc][1], ax, b1x);
                ffma2(accO[cc][1], ay, b1y);
            }
        }
    }

    // ---- epilogue ----
#pragma unroll
    for (int cc = 0; cc < 8; cc++)
#pragma unroll
        for (int ok = 0; ok < 2; ok++) {
            float2 f = unp(accO[cc][ok]);
            float val = f.x + f.y;
            int go = otile + lane + (ok << 5);
            if (go < NPT)
                Op[((size_t)((sp*BB + b)*CCH + c0 + cc))*OPAD + go] = val;
        }
    if (lane == 0) {
#pragma unroll
        for (int r = 0; r < 4; r++) {
            int go = otile + o0 + r;
            if (go < NPT) {
                Mm[(sp*BB + b)*OPAD + go] = mr[r];
                Lp[(sp*BB + b)*OPAD + go] = lr[r];
            }
        }
    }
}

// ---------------- fused head: norm + c1 + c2 + c3 ----------------
struct HeadS {
    float xt[CCH][68];
    float cw1[32][128];
    float cw2[32][32];
    float cw3[32];
    float b1[32], b2[32];
    float ph1[64][33];
    float ph2[64][33];
    float sinv[64];
};

__global__ void __launch_bounds__(256) head_kernel(const float* __restrict__ X,
        const float* __restrict__ c1W, const float* __restrict__ c1b,
        const float* __restrict__ c2W, const float* __restrict__ c2b,
        const float* __restrict__ c3W, const float* __restrict__ c3b,
        float* __restrict__ out)
{
    extern __shared__ char sraw[];
    HeadS& S = *reinterpret_cast<HeadS*>(sraw);
    int tid = threadIdx.x;
    int n0 = blockIdx.x << 6, b = blockIdx.y;

    for (int i = tid; i < 32*128; i += 256) S.cw1[i >> 7][i & 127] = c1W[i];
    for (int i = tid; i < 32*32;  i += 256) S.cw2[i >> 5][i & 31]  = c2W[i];
    if (tid < 32) { S.cw3[tid] = c3W[tid]; S.b1[tid] = c1b[tid]; S.b2[tid] = c2b[tid]; }
    for (int t = tid; t < CCH*16; t += 256) {
        int row = t >> 4, j4 = (t & 15) << 2;
        float4 v = make_float4(0.f,0.f,0.f,0.f);
        if (n0 + j4 < NPT) v = *(const float4*)&X[((size_t)(b*CCH + row))*NPT + n0 + j4];
        *(float4*)&S.xt[row][j4] = v;
    }
    __syncthreads();

    int p = tid >> 2, qd = tid & 3;
    float ss = 0.f;
    for (int c = qd*32; c < qd*32 + 32; c++) { float v = S.xt[c][p]; ss += v*v; }
    ss += __shfl_xor_sync(0xffffffffu, ss, 1, 4);
    ss += __shfl_xor_sync(0xffffffffu, ss, 2, 4);
    if (qd == 0) S.sinv[p] = 1.f / fmaxf(sqrtf(ss), 1e-12f);

#pragma unroll
    for (int jj = 0; jj < 8; jj++) {
        int j = qd*8 + jj;
        float a = S.b1[j];
        for (int c = 0; c < CCH; c++) a += S.cw1[j][c] * S.xt[c][p];
        S.ph1[p][j] = fmaxf(a, 0.f);
    }
    __syncthreads();
#pragma unroll
    for (int jj = 0; jj < 8; jj++) {
        int j = qd*8 + jj;
        float a = S.b2[j];
        for (int c = 0; c < 32; c++) a += S.cw2[j][c] * S.ph1[p][c];
        S.ph2[p][j] = fmaxf(a, 0.f);
    }
    __syncthreads();
    if (qd == 0) {
        float a = c3b[0];
        for (int c = 0; c < 32; c++) a += S.cw3[c] * S.ph2[p][c];
        int n = n0 + p;
        if (n < NPT) out[b*NPT + n] = a;
    }
    float* dst = out + BB*NPT;
    for (int t = tid; t < CCH*16; t += 256) {
        int row = t >> 4, j4 = (t & 15) << 2;
#pragma unroll
        for (int e = 0; e < 4; e++) {
            int n = n0 + j4 + e;
            if (n < NPT)
                dst[((size_t)(b*CCH + row))*NPT + n] = S.xt[row][j4 + e] * S.sinv[j4 + e];
        }
    }
}

// ======================= host launcher =======================
extern "C" void kernel_launch(void* const* d_in, const int* in_sizes, int n_in,
                              void* d_out, int out_size)
{
    const float* corr    = (const float*)d_in[0];
    const float* src     = (const float*)d_in[1];
    const float* tgt     = (const float*)d_in[2];
    const float* iW      = (const float*)d_in[3];
    const float* ib      = (const float*)d_in[4];
    const float* pcnW    = (const float*)d_in[5];
    const float* pcnb    = (const float*)d_in[6];
    const float* pcng    = (const float*)d_in[7];
    const float* pcnbeta = (const float*)d_in[8];
    const float* qW  = (const float*)d_in[9];  const float* qb  = (const float*)d_in[10];
    const float* kW  = (const float*)d_in[11]; const float* kb  = (const float*)d_in[12];
    const float* vW  = (const float*)d_in[13]; const float* vb  = (const float*)d_in[14];
    const float* m1W = (const float*)d_in[15]; const float* m1b = (const float*)d_in[16];
    const float* m1g = (const float*)d_in[17]; const float* m1beta = (const float*)d_in[18];
    const float* m2W = (const float*)d_in[19]; const float* m2b = (const float*)d_in[20];
    const float* m2g = (const float*)d_in[21]; const float* m2beta = (const float*)d_in[22];
    const float* m3W = (const float*)d_in[23]; const float* m3b = (const float*)d_in[24];
    const float* c1W = (const float*)d_in[25]; const float* c1b = (const float*)d_in[26];
    const float* c2W = (const float*)d_in[27]; const float* c2b = (const float*)d_in[28];
    const float* c3W = (const float*)d_in[29]; const float* c3b = (const float*)d_in[30];
    float* out = (float*)d_out;

    float *x, *y, *v, *m, *h, *qt, *kt, *Op, *Lp, *Mm, *ps, *pq;
    float *scl, *shf, *scl1, *shf1, *scl2, *shf2;
    cudaGetSymbolAddress((void**)&x,  g_x);
    cudaGetSymbolAddress((void**)&y,  g_y);
    cudaGetSymbolAddress((void**)&v,  g_v);
    cudaGetSymbolAddress((void**)&m,  g_m);
    cudaGetSymbolAddress((void**)&h,  g_h);
    cudaGetSymbolAddress((void**)&qt, g_qt);
    cudaGetSymbolAddress((void**)&kt, g_kt);
    cudaGetSymbolAddress((void**)&Op, g_Op);
    cudaGetSymbolAddress((void**)&Lp, g_Lp);
    cudaGetSymbolAddress((void**)&Mm, g_Mm);
    cudaGetSymbolAddress((void**)&ps, g_ps);
    cudaGetSymbolAddress((void**)&pq, g_pq);
    cudaGetSymbolAddress((void**)&scl,  g_scl);  cudaGetSymbolAddress((void**)&shf,  g_shf);
    cudaGetSymbolAddress((void**)&scl1, g_scl1); cudaGetSymbolAddress((void**)&shf1, g_shf1);
    cudaGetSymbolAddress((void**)&scl2, g_scl2); cudaGetSymbolAddress((void**)&shf2, g_shf2);

    const int nT64 = (NPT + 63) / 64;        // 47
    const int smemFlash = (int)sizeof(FlashS);
    const int smemHead  = (int)sizeof(HeadS);
    cudaFuncSetAttribute(flash_kernel, cudaFuncAttributeMaxDynamicSharedMemorySize, smemFlash);
    cudaFuncSetAttribute(head_kernel,  cudaFuncAttributeMaxDynamicSharedMemorySize, smemHead);

    dim3 blk(256);
    init_conv_kernel<<<(BB*NPT + 127)/128, 128>>>(corr, iW, ib, x);

    for (int l = 0; l < LL; l++) {
        // PointCN conv (pre-BN output y) + stats partials
        conv_kernel<0,0,true><<<dim3(nT64,2,BB), blk>>>(
            x, pcnW + (size_t)l*CCH*CCH, pcnb + l*CCH,
            nullptr, nullptr, nullptr, nullptr, nullptr,
            y, ps, pq, CCH, CCH);
        bnred_kernel<<<CCH, 32>>>(ps, pq, pcng + l*CCH, pcnbeta + l*CCH, scl, shf);

        // fused q/k/v (564 blocks; affine+relu on load; q,k transposed out)
        qkv_kernel<<<dim3(nT64,6,BB), blk>>>(
            y, qW + (size_t)l*CCH*CCH, kW + (size_t)l*CCH*CCH, vW + (size_t)l*CCH*CCH,
            qb + l*CCH, kb + l*CCH, vb + l*CCH, scl, shf, qt, kt, v);

        // flash attention
        flash_kernel<<<dim3(nT64, ISPLIT, BB), 512, smemFlash>>>(qt, kt, v, src, tgt, Op, Lp, Mm);

        // m1: merge partials on load (weights computed in-block from Mm/Lp), stats out
        conv_kernel<3,0,true><<<dim3(nT64,1,BB), blk>>>(
            Op, m1W + (size_t)l*CH*CCH, m1b + l*CH,
            nullptr, nullptr, nullptr, Mm, Lp,
            m, ps, pq, CCH, CH);
        bnred_kernel<<<CH, 32>>>(ps, pq, m1g + l*CH, m1beta + l*CH, scl1, shf1);

        // m2: affine1 on load, stats out
        conv_kernel<1,0,true><<<dim3(nT64,1,BB), blk>>>(
            m, m2W + (size_t)l*CH*CH, m2b + l*CH,
            scl1, shf1, nullptr, nullptr, nullptr,
            h, ps, pq, CH, CH);
        bnred_kernel<<<CH, 32>>>(ps, pq, m2g + l*CH, m2beta + l*CH, scl2, shf2);

        // m3: affine2 on load, residual = relu(affine_pcn(y)), out -> x
        conv_kernel<1,2,false><<<dim3(nT64,2,BB), blk>>>(
            h, m3W + (size_t)l*CCH*CH, m3b + l*CCH,
            scl2, shf2, y, scl, shf,
            x, nullptr, nullptr, CH, CCH);
    }

    head_kernel<<<dim3(nT64, BB), 256, smemHead>>>(x, c1W, c1b, c2W, c2b, c3W, c3b, out);
}

// round 12
// speedup vs baseline: 2.1893x; 1.0762x over previous
#include <cuda_runtime.h>
#include <math.h>

#define NPT 3000
#define BB 2
#define CCH 128
#define CH 64
#define LL 6
#define EPSBN 1e-5f
#define ATT_SCALE 0.08838834764831845f  // 1/sqrt(128)

#define TQ 64
#define TI 128
#define ISPLIT 3
#define SPLEN 1000
#define OPAD 3008
#define NEGBIG -1e30f

typedef unsigned long long ull;

__device__ __forceinline__ void ffma2(ull &d, ull a, ull b) {
    asm("fma.rn.f32x2 %0, %1, %2, %0;" : "+l"(d) : "l"(a), "l"(b));
}
__device__ __forceinline__ void mulf2(ull &d, ull f) {
    asm("mul.rn.f32x2 %0, %0, %1;" : "+l"(d) : "l"(f));
}
__device__ __forceinline__ float2 unp(ull v) {
    unsigned lo, hi;
    asm("mov.b64 {%0,%1}, %2;" : "=r"(lo), "=r"(hi) : "l"(v));
    return make_float2(__uint_as_float(lo), __uint_as_float(hi));
}
__device__ __forceinline__ ull packdup(float x) {
    ull r; unsigned u = __float_as_uint(x);
    asm("mov.b64 %0, {%1, %1};" : "=l"(r) : "r"(u));
    return r;
}
__device__ __forceinline__ ull d2u(double d) { return __double_as_longlong(d); }
__device__ __forceinline__ float sqrt_approx(float x) {
    float r; asm("sqrt.approx.f32 %0, %1;" : "=f"(r) : "f"(x)); return r;
}

// ---------------- device scratch ----------------
__device__ float g_x[BB*CCH*NPT];
__device__ float g_y[BB*CCH*NPT];
__device__ float g_v[BB*CCH*NPT];
__device__ float g_m[BB*CCH*NPT];
__device__ float g_h[BB*CCH*NPT];
__device__ float g_qt[(size_t)BB*NPT*CCH];
__device__ float g_kt[(size_t)BB*NPT*CCH];
__device__ float g_Op[(size_t)ISPLIT*BB*CCH*OPAD];
__device__ float g_Lp[ISPLIT*BB*OPAD];
__device__ float g_Mm[ISPLIT*BB*OPAD];
__device__ float g_ps[CCH*64], g_pq[CCH*64];
__device__ float g_scl[CCH],  g_shf[CCH];
__device__ float g_scl1[CCH], g_shf1[CCH];
__device__ float g_scl2[CCH], g_shf2[CCH];

// ---------------- init embedding ----------------
__global__ void init_conv_kernel(const float* __restrict__ corr, const float* __restrict__ W,
                                 const float* __restrict__ bias, float* __restrict__ X)
{
    __shared__ float Ws[CCH*6];
    __shared__ float bs[CCH];
    int tid = threadIdx.x;
    for (int i = tid; i < CCH*6; i += blockDim.x) Ws[i] = W[i];
    for (int i = tid; i < CCH;   i += blockDim.x) bs[i] = bias[i];
    __syncthreads();
    int idx = blockIdx.x * blockDim.x + tid;
    if (idx >= BB*NPT) return;
    int b = idx / NPT, n = idx - b*NPT;
    float cp[6];
#pragma unroll
    for (int j = 0; j < 6; j++) cp[j] = corr[(size_t)idx*6 + j];
    for (int co = 0; co < CCH; co++) {
        float a = bs[co];
#pragma unroll
        for (int j = 0; j < 6; j++) a += Ws[co*6 + j] * cp[j];
        X[((size_t)b*CCH + co)*NPT + n] = a;
    }
}

// ---------------- conv smem ----------------
template<int CIN> struct ConvS {
    float Xs[128][CIN + 4];   // [n][ci], stride ≡ 4 mod 32 -> conflict-free phases
    float Ws[32][CIN + 4];    // [co][ci]
    float sA[CCH], sB[CCH];
    float swc[ISPLIT][128];
};

// ---------------- pointwise conv (warp-broadcast weights, ci-pair packing) ----------------
// INMODE: 0 plain, 1 relu(scl*x+shf) on input, 3 weighted 3-way Op merge (weights from Mm/Lp in rscl/rshf)
// RES:    0 none, 2 add relu(rscl*R+rshf)
// STATS:  per-(co, n-tile) partial sum/sumsq
template<int CIN, int INMODE, int RES, bool STATS>
__global__ void __launch_bounds__(256) conv_kernel(const float* __restrict__ X,
        const float* __restrict__ W, const float* __restrict__ bias,
        const float* __restrict__ scl, const float* __restrict__ shf,
        const float* __restrict__ R, const float* __restrict__ rscl,
        const float* __restrict__ rshf,
        float* __restrict__ Y, float* __restrict__ psum, float* __restrict__ psq,
        int Cout)
{
    extern __shared__ char sraw[];
    ConvS<CIN>& S = *reinterpret_cast<ConvS<CIN>*>(sraw);
    const int tid = threadIdx.x;
    const int b = blockIdx.z, co0 = blockIdx.y << 5, n0 = blockIdx.x << 7;

    if (INMODE == 1) {
        if (tid < CIN) { S.sA[tid] = scl[tid]; S.sB[tid] = shf[tid]; }
    }
    if (INMODE == 3) {
        if (tid < 128) {
            int n = n0 + tid;
            float w0 = 0.f, w1 = 0.f, w2 = 0.f;
            if (n < NPT) {
                float m0 = rscl[(0*BB + b)*OPAD + n];
                float m1v = rscl[(1*BB + b)*OPAD + n];
                float m2v = rscl[(2*BB + b)*OPAD + n];
                float l0 = rshf[(0*BB + b)*OPAD + n];
                float l1 = rshf[(1*BB + b)*OPAD + n];
                float l2 = rshf[(2*BB + b)*OPAD + n];
                float Mx = fmaxf(fmaxf(m0, m1v), m2v);
                w0 = __expf(m0 - Mx); w1 = __expf(m1v - Mx); w2 = __expf(m2v - Mx);
                float inv = 1.f / (l0*w0 + l1*w1 + l2*w2);
                w0 *= inv; w1 *= inv; w2 *= inv;
            }
            S.swc[0][tid] = w0; S.swc[1][tid] = w1; S.swc[2][tid] = w2;
        }
    }
    if (INMODE != 0) __syncthreads();

    // ---- W tile fill [32][CIN] ----
#pragma unroll
    for (int j = 0; j < 32*CIN/1024; j++) {
        int idx = tid + (j << 8);
        int row = idx / (CIN/4), c4 = (idx % (CIN/4)) << 2;
        *(float4*)&S.Ws[row][c4] = *(const float4*)&W[(size_t)(co0 + row)*CIN + c4];
    }
    // ---- X tile fill, transposed to [n][ci] (lanes->ci: conflict-free STS) ----
#pragma unroll
    for (int j = 0; j < 128*CIN/1024; j++) {
        int idx = tid + (j << 8);
        int ci = idx & (CIN - 1);
        int n4 = (idx / CIN) << 2;
        float4 v = make_float4(0.f,0.f,0.f,0.f);
        if (n0 + n4 < NPT) {
            if (INMODE == 3) {
                const size_t sstr = (size_t)BB*CCH*OPAD;
                const float* base = X + ((size_t)(b*CCH + ci))*OPAD + n0 + n4;
                float4 a0 = *(const float4*)&base[0];
                float4 a1 = *(const float4*)&base[sstr];
                float4 a2 = *(const float4*)&base[2*sstr];
                v.x = a0.x*S.swc[0][n4]   + a1.x*S.swc[1][n4]   + a2.x*S.swc[2][n4];
                v.y = a0.y*S.swc[0][n4+1] + a1.y*S.swc[1][n4+1] + a2.y*S.swc[2][n4+1];
                v.z = a0.z*S.swc[0][n4+2] + a1.z*S.swc[1][n4+2] + a2.z*S.swc[2][n4+2];
                v.w = a0.w*S.swc[0][n4+3] + a1.w*S.swc[1][n4+3] + a2.w*S.swc[2][n4+3];
            } else {
                v = *(const float4*)&X[((size_t)(b*CIN + ci))*NPT + n0 + n4];
                if (INMODE == 1) {
                    float sa = S.sA[ci], sb = S.sB[ci];
                    v.x = fmaxf(fmaf(sa, v.x, sb), 0.f);
                    v.y = fmaxf(fmaf(sa, v.y, sb), 0.f);
                    v.z = fmaxf(fmaf(sa, v.z, sb), 0.f);
                    v.w = fmaxf(fmaf(sa, v.w, sb), 0.f);
                }
            }
        }
        S.Xs[n4][ci] = v.x; S.Xs[n4+1][ci] = v.y;
        S.Xs[n4+2][ci] = v.z; S.Xs[n4+3][ci] = v.w;
    }
    __syncthreads();

    const int warp = tid >> 5, lane = tid & 31;
    const int r0 = warp << 2;
    ull acc[4][4];
#pragma unroll
    for (int r = 0; r < 4; r++)
#pragma unroll
        for (int s = 0; s < 4; s++) acc[r][s] = 0ull;

#pragma unroll 8
    for (int cq = 0; cq < CIN; cq += 4) {
        double2 wv[4], xv[4];
#pragma unroll
        for (int r = 0; r < 4; r++) wv[r] = *(const double2*)&S.Ws[r0 + r][cq];
#pragma unroll
        for (int s = 0; s < 4; s++) xv[s] = *(const double2*)&S.Xs[lane + (s << 5)][cq];
#pragma unroll
        for (int r = 0; r < 4; r++) {
            ull ax = d2u(wv[r].x), ay = d2u(wv[r].y);
#pragma unroll
            for (int s = 0; s < 4; s++) {
                ffma2(acc[r][s], ax, d2u(xv[s].x));
                ffma2(acc[r][s], ay, d2u(xv[s].y));
            }
        }
    }

    float vals[4][4];
#pragma unroll
    for (int r = 0; r < 4; r++) {
        float bv = bias[co0 + r0 + r];
#pragma unroll
        for (int s = 0; s < 4; s++) {
            float2 f = unp(acc[r][s]);
            vals[r][s] = f.x + f.y + bv;
        }
    }

    if (STATS) {
#pragma unroll
        for (int r = 0; r < 4; r++) {
            float s_ = 0.f, sq = 0.f;
#pragma unroll
            for (int s = 0; s < 4; s++) {
                int n = n0 + lane + (s << 5);
                if (n < NPT) { s_ += vals[r][s]; sq += vals[r][s]*vals[r][s]; }
            }
#pragma unroll
            for (int o = 16; o; o >>= 1) {
                s_ += __shfl_xor_sync(0xffffffffu, s_, o);
                sq += __shfl_xor_sync(0xffffffffu, sq, o);
            }
            if (lane == 0) {
                int co = co0 + r0 + r;
                int p = b*24 + blockIdx.x;
                psum[co*64 + p] = s_;
                psq[co*64 + p]  = sq;
            }
        }
    }

#pragma unroll
    for (int s = 0; s < 4; s++) {
        int n = n0 + lane + (s << 5);
        if (n >= NPT) continue;
#pragma unroll
        for (int r = 0; r < 4; r++) {
            int co = co0 + r0 + r;
            float v = vals[r][s];
            size_t off = ((size_t)(b*Cout + co))*NPT + n;
            if (RES == 2) {
                float rr = R[off];
                v += fmaxf(fmaf(rscl[co], rr, rshf[co]), 0.f);
            }
            Y[off] = v;
        }
    }
}

// ---------------- fused q/k/v conv (576 blocks), same mainloop structure ----------------
__global__ void __launch_bounds__(256) qkv_kernel(const float* __restrict__ X,
        const float* __restrict__ qW, const float* __restrict__ kW, const float* __restrict__ vW,
        const float* __restrict__ qb, const float* __restrict__ kb, const float* __restrict__ vb,
        const float* __restrict__ scl, const float* __restrict__ shf,
        float* __restrict__ qt, float* __restrict__ kt, float* __restrict__ v)
{
    extern __shared__ char sraw[];
    ConvS<CCH>& S = *reinterpret_cast<ConvS<CCH>*>(sraw);
    const int tid = threadIdx.x;
    const int sel = blockIdx.y >> 2;
    const float* W    = (sel == 0) ? qW : (sel == 1) ? kW : vW;
    const float* bias = (sel == 0) ? qb : (sel == 1) ? kb : vb;
    const int b = blockIdx.z, co0 = (blockIdx.y & 3) << 5, n0 = blockIdx.x << 7;

    if (tid < CCH) { S.sA[tid] = scl[tid]; S.sB[tid] = shf[tid]; }
    __syncthreads();

#pragma unroll
    for (int j = 0; j < 4; j++) {
        int idx = tid + (j << 8);
        int row = idx >> 5, c4 = (idx & 31) << 2;
        *(float4*)&S.Ws[row][c4] = *(const float4*)&W[(size_t)(co0 + row)*CCH + c4];
    }
#pragma unroll
    for (int j = 0; j < 16; j++) {
        int idx = tid + (j << 8);
        int ci = idx & 127;
        int n4 = (idx >> 7) << 2;
        float4 vv = make_float4(0.f,0.f,0.f,0.f);
        if (n0 + n4 < NPT) {
            vv = *(const float4*)&X[((size_t)(b*CCH + ci))*NPT + n0 + n4];
            float sa = S.sA[ci], sb = S.sB[ci];
            vv.x = fmaxf(fmaf(sa, vv.x, sb), 0.f);
            vv.y = fmaxf(fmaf(sa, vv.y, sb), 0.f);
            vv.z = fmaxf(fmaf(sa, vv.z, sb), 0.f);
            vv.w = fmaxf(fmaf(sa, vv.w, sb), 0.f);
        }
        S.Xs[n4][ci] = vv.x; S.Xs[n4+1][ci] = vv.y;
        S.Xs[n4+2][ci] = vv.z; S.Xs[n4+3][ci] = vv.w;
    }
    __syncthreads();

    const int warp = tid >> 5, lane = tid & 31;
    const int r0 = warp << 2;
    ull acc[4][4];
#pragma unroll
    for (int r = 0; r < 4; r++)
#pragma unroll
        for (int s = 0; s < 4; s++) acc[r][s] = 0ull;

#pragma unroll 8
    for (int cq = 0; cq < CCH; cq += 4) {
        double2 wv[4], xv[4];
#pragma unroll
        for (int r = 0; r < 4; r++) wv[r] = *(const double2*)&S.Ws[r0 + r][cq];
#pragma unroll
        for (int s = 0; s < 4; s++) xv[s] = *(const double2*)&S.Xs[lane + (s << 5)][cq];
#pragma unroll
        for (int r = 0; r < 4; r++) {
            ull ax = d2u(wv[r].x), ay = d2u(wv[r].y);
#pragma unroll
            for (int s = 0; s < 4; s++) {
                ffma2(acc[r][s], ax, d2u(xv[s].x));
                ffma2(acc[r][s], ay, d2u(xv[s].y));
            }
        }
    }

    float vals[4][4];
#pragma unroll
    for (int r = 0; r < 4; r++) {
        float bv = bias[co0 + r0 + r];
#pragma unroll
        for (int s = 0; s < 4; s++) {
            float2 f = unp(acc[r][s]);
            vals[r][s] = f.x + f.y + bv;
        }
    }

    if (sel < 2) {
        float* base = ((sel == 0) ? qt : kt) + (size_t)b*NPT*CCH;
#pragma unroll
        for (int s = 0; s < 4; s++) {
            int n = n0 + lane + (s << 5);
            if (n >= NPT) continue;
            *(float4*)&base[(size_t)n*CCH + co0 + r0] =
                make_float4(vals[0][s], vals[1][s], vals[2][s], vals[3][s]);
        }
    } else {
#pragma unroll
        for (int s = 0; s < 4; s++) {
            int n = n0 + lane + (s << 5);
            if (n >= NPT) continue;
#pragma unroll
            for (int r = 0; r < 4; r++)
                v[((size_t)(b*CCH + co0 + r0 + r))*NPT + n] = vals[r][s];
        }
    }
}

// ---------------- partial-sum reduce -> per-channel affine ----------------
__global__ void bnred_kernel(const float* __restrict__ psum, const float* __restrict__ psq,
                             const float* __restrict__ g, const float* __restrict__ beta,
                             float* __restrict__ scl, float* __restrict__ shf)
{
    int c = blockIdx.x, t = threadIdx.x;
    float s = 0.f, q = 0.f;
    for (int p = t; p < 48; p += 32) { s += psum[c*64 + p]; q += psq[c*64 + p]; }
#pragma unroll
    for (int o = 16; o; o >>= 1) {
        s += __shfl_xor_sync(0xffffffffu, s, o);
        q += __shfl_xor_sync(0xffffffffu, q, o);
    }
    if (t == 0) {
        float inv = 1.f / (float)(BB*NPT);
        float m = s * inv;
        float var = q * inv - m*m;
        float rs = rsqrtf(var + EPSBN);
        scl[c] = g[c] * rs;
        shf[c] = beta[c] - m * g[c] * rs;
    }
}

// ---------------- flash attention (unchanged from R10 passing version) ----------------
struct FlashS {
    float Qt[TQ][132];
    float KV[CCH*132];
    float Pd[TQ][132];
    float pOs[TQ][6];
    float pI[TI][6];
    float alph[TQ];
};

__global__ void __launch_bounds__(512, 1) flash_kernel(
    const float* __restrict__ Qt, const float* __restrict__ Kt,
    const float* __restrict__ V,
    const float* __restrict__ src, const float* __restrict__ tgt,
    float* __restrict__ Op, float* __restrict__ Lp, float* __restrict__ Mm)
{
    extern __shared__ char smem_raw[];
    FlashS& S = *reinterpret_cast<FlashS*>(smem_raw);
    int tid = threadIdx.x;
    int otile = blockIdx.x * TQ;
    int sp = blockIdx.y, b = blockIdx.z;
    int sbase = sp * SPLEN;
    int send  = min(sbase + SPLEN, NPT);
    int warp = tid >> 5, lane = tid & 31;
    int o0 = warp << 2;
    int c0 = warp << 3;

#pragma unroll
    for (int j = 0; j < 4; j++) {
        int idx = tid + (j << 9);
        int row = idx >> 5, c4 = (idx & 31) << 2;
        int go = otile + row;
        float4 qv = make_float4(0.f,0.f,0.f,0.f);
        if (go < NPT) qv = *(const float4*)&Qt[((size_t)b*NPT + go)*CCH + c4];
        *(float4*)&S.Qt[row][c4] = qv;
    }
    if (tid < TQ) {
        int go = otile + tid;
        if (go < NPT) {
#pragma unroll
            for (int e = 0; e < 3; e++) {
                S.pOs[tid][e]   = src[((size_t)b*NPT + go)*3 + e];
                S.pOs[tid][3+e] = tgt[((size_t)b*NPT + go)*3 + e];
            }
        } else {
#pragma unroll
            for (int e = 0; e < 6; e++) S.pOs[tid][e] = 0.f;
        }
    }
    float mr[4] = {NEGBIG, NEGBIG, NEGBIG, NEGBIG};
    float lr[4] = {0.f, 0.f, 0.f, 0.f};
    ull accO[8][2];
#pragma unroll
    for (int i = 0; i < 8; i++) { accO[i][0] = 0ull; accO[i][1] = 0ull; }

    const int nch = (send - sbase + TI - 1) / TI;
#pragma unroll 1
    for (int ch = 0; ch < nch; ch++) {
        int ibase = sbase + ch * TI;
        __syncthreads();
#pragma unroll
        for (int j = 0; j < 8; j++) {
            int idx = tid + (j << 9);
            int row = idx >> 5, c4 = (idx & 31) << 2;
            int gi = ibase + row;
            float4 kv = make_float4(0.f,0.f,0.f,0.f);
            if (gi < send) kv = *(const float4*)&Kt[((size_t)b*NPT + gi)*CCH + c4];
            *(float4*)&S.KV[row*132 + c4] = kv;
        }
        if (tid < TI) {
            int gi = ibase + tid;
            if (gi < send) {
#pragma unroll
                for (int e = 0; e < 3; e++) {
                    S.pI[tid][e]   = src[((size_t)b*NPT + gi)*3 + e];
                    S.pI[tid][3+e] = tgt[((size_t)b*NPT + gi)*3 + e];
                }
            } else {
#pragma unroll
                for (int e = 0; e < 6; e++) S.pI[tid][e] = 0.f;
            }
        }
        __syncthreads();

        ull sacc[4][4];
#pragma unroll
        for (int r = 0; r < 4; r++)
#pragma unroll
            for (int s = 0; s < 4; s++) sacc[r][s] = 0ull;
#pragma unroll 4
        for (int cq = 0; cq < CCH; cq += 4) {
            double2 qv[4], kv[4];
#pragma unroll
            for (int r = 0; r < 4; r++) qv[r] = *(const double2*)&S.Qt[o0 + r][cq];
#pragma unroll
            for (int s = 0; s < 4; s++) kv[s] = *(const double2*)&S.KV[(lane + (s << 5))*132 + cq];
#pragma unroll
            for (int r = 0; r < 4; r++) {
                ull ax = d2u(qv[r].x), ay = d2u(qv[r].y);
#pragma unroll
                for (int s = 0; s < 4; s++) {
                    ffma2(sacc[r][s], ax, d2u(kv[s].x));
                    ffma2(sacc[r][s], ay, d2u(kv[s].y));
                }
            }
        }

        float sv[4][4];
#pragma unroll
        for (int r = 0; r < 4; r++)
#pragma unroll
            for (int s = 0; s < 4; s++) {
                float2 f = unp(sacc[r][s]);
                sv[r][s] = f.x + f.y;
            }
#pragma unroll
        for (int s = 0; s < 4; s++) {
            int il = lane + (s << 5);
            bool valid = (ibase + il) < send;
            float pi0 = S.pI[il][0], pi1 = S.pI[il][1], pi2 = S.pI[il][2];
            float pi3 = S.pI[il][3], pi4 = S.pI[il][4], pi5 = S.pI[il][5];
#pragma unroll
            for (int r = 0; r < 4; r++) {
                float dx = S.pOs[o0+r][0] - pi0, dy = S.pOs[o0+r][1] - pi1, dz = S.pOs[o0+r][2] - pi2;
                float ds = sqrt_approx(dx*dx + dy*dy + dz*dz);
                dx = S.pOs[o0+r][3] - pi3; dy = S.pOs[o0+r][4] - pi4; dz = S.pOs[o0+r][5] - pi5;
                float dt = sqrt_approx(dx*dx + dy*dy + dz*dz);
                float d = ds - dt;
                float scv = fmaxf(1.f - d*d, 0.f) * ATT_SCALE;
                sv[r][s] = valid ? sv[r][s] * scv : NEGBIG;
            }
        }
#pragma unroll
        for (int r = 0; r < 4; r++) {
            float mx = fmaxf(fmaxf(sv[r][0], sv[r][1]), fmaxf(sv[r][2], sv[r][3]));
#pragma unroll
            for (int s = 16; s; s >>= 1) mx = fmaxf(mx, __shfl_xor_sync(0xffffffffu, mx, s));
            float mnew = fmaxf(mr[r], mx);
            float al = __expf(mr[r] - mnew);
            mr[r] = mnew;
            float psum = 0.f;
#pragma unroll
            for (int s = 0; s < 4; s++) {
                float p = __expf(sv[r][s] - mnew);
                S.Pd[o0 + r][lane + (s << 5)] = p;
                psum += p;
            }
#pragma unroll
            for (int s = 16; s; s >>= 1) psum += __shfl_xor_sync(0xffffffffu, psum, s);
            lr[r] = lr[r] * al + psum;
            if (lane == 0) S.alph[o0 + r] = al;
        }
        __syncthreads();

#pragma unroll
        for (int j = 0; j < 8; j++) {
            int idx = tid + (j << 9);
            int row = idx >> 5, i4 = (idx & 31) << 2;
            int gi = ibase + i4;
            float4 vv = make_float4(0.f,0.f,0.f,0.f);
            if (gi < send) vv = *(const float4*)&V[((size_t)(b*CCH + row))*NPT + gi];
            *(float4*)&S.KV[row*132 + i4] = vv;
        }
        __syncthreads();

        {
            ull ad0 = packdup(S.alph[lane]);
            ull ad1 = packdup(S.alph[lane + 32]);
#pragma unroll
            for (int cc = 0; cc < 8; cc++) { mulf2(accO[cc][0], ad0); mulf2(accO[cc][1], ad1); }
        }
#pragma unroll 2
        for (int iq = 0; iq < TI; iq += 4) {
            double2 b0 = *(const double2*)&S.Pd[lane][iq];
            double2 b1 = *(const double2*)&S.Pd[lane + 32][iq];
            ull b0x = d2u(b0.x), b0y = d2u(b0.y), b1x = d2u(b1.x), b1y = d2u(b1.y);
#pragma unroll
            for (int cc = 0; cc < 8; cc++) {
                double2 av = *(const double2*)&S.KV[(c0 + cc)*132 + iq];
                ull ax = d2u(av.x), ay = d2u(av.y);
                ffma2(accO[cc][0], ax, b0x);
                ffma2(accO[cc][0], ay, b0y);
                ffma2(accO[cc][1], ax, b1x);
                ffma2(accO[cc][1], ay, b1y);
            }
        }
    }

#pragma unroll
    for (int cc = 0; cc < 8; cc++)
#pragma unroll
        for (int ok = 0; ok < 2; ok++) {
            float2 f = unp(accO[cc][ok]);
            float val = f.x + f.y;
            int go = otile + lane + (ok << 5);
            if (go < NPT)
                Op[((size_t)((sp*BB + b)*CCH + c0 + cc))*OPAD + go] = val;
        }
    if (lane == 0) {
#pragma unroll
        for (int r = 0; r < 4; r++) {
            int go = otile + o0 + r;
            if (go < NPT) {
                Mm[(sp*BB + b)*OPAD + go] = mr[r];
                Lp[(sp*BB + b)*OPAD + go] = lr[r];
            }
        }
    }
}

// ---------------- fused head: norm + c1 + c2 + c3 ----------------
struct HeadS {
    float xt[CCH][68];
    float cw1[32][128];
    float cw2[32][32];
    float cw3[32];
    float b1[32], b2[32];
    float ph1[64][33];
    float ph2[64][33];
    float sinv[64];
};

__global__ void __launch_bounds__(256) head_kernel(const float* __restrict__ X,
        const float* __restrict__ c1W, const float* __restrict__ c1b,
        const float* __restrict__ c2W, const float* __restrict__ c2b,
        const float* __restrict__ c3W, const float* __restrict__ c3b,
        float* __restrict__ out)
{
    extern __shared__ char sraw[];
    HeadS& S = *reinterpret_cast<HeadS*>(sraw);
    int tid = threadIdx.x;
    int n0 = blockIdx.x << 6, b = blockIdx.y;

    for (int i = tid; i < 32*128; i += 256) S.cw1[i >> 7][i & 127] = c1W[i];
    for (int i = tid; i < 32*32;  i += 256) S.cw2[i >> 5][i & 31]  = c2W[i];
    if (tid < 32) { S.cw3[tid] = c3W[tid]; S.b1[tid] = c1b[tid]; S.b2[tid] = c2b[tid]; }
    for (int t = tid; t < CCH*16; t += 256) {
        int row = t >> 4, j4 = (t & 15) << 2;
        float4 v = make_float4(0.f,0.f,0.f,0.f);
        if (n0 + j4 < NPT) v = *(const float4*)&X[((size_t)(b*CCH + row))*NPT + n0 + j4];
        *(float4*)&S.xt[row][j4] = v;
    }
    __syncthreads();

    int p = tid >> 2, qd = tid & 3;
    float ss = 0.f;
    for (int c = qd*32; c < qd*32 + 32; c++) { float v = S.xt[c][p]; ss += v*v; }
    ss += __shfl_xor_sync(0xffffffffu, ss, 1, 4);
    ss += __shfl_xor_sync(0xffffffffu, ss, 2, 4);
    if (qd == 0) S.sinv[p] = 1.f / fmaxf(sqrtf(ss), 1e-12f);

#pragma unroll
    for (int jj = 0; jj < 8; jj++) {
        int j = qd*8 + jj;
        float a = S.b1[j];
        for (int c = 0; c < CCH; c++) a += S.cw1[j][c] * S.xt[c][p];
        S.ph1[p][j] = fmaxf(a, 0.f);
    }
    __syncthreads();
#pragma unroll
    for (int jj = 0; jj < 8; jj++) {
        int j = qd*8 + jj;
        float a = S.b2[j];
        for (int c = 0; c < 32; c++) a += S.cw2[j][c] * S.ph1[p][c];
        S.ph2[p][j] = fmaxf(a, 0.f);
    }
    __syncthreads();
    if (qd == 0) {
        float a = c3b[0];
        for (int c = 0; c < 32; c++) a += S.cw3[c] * S.ph2[p][c];
        int n = n0 + p;
        if (n < NPT) out[b*NPT + n] = a;
    }
    float* dst = out + BB*NPT;
    for (int t = tid; t < CCH*16; t += 256) {
        int row = t >> 4, j4 = (t & 15) << 2;
#pragma unroll
        for (int e = 0; e < 4; e++) {
            int n = n0 + j4 + e;
            if (n < NPT)
                dst[((size_t)(b*CCH + row))*NPT + n] = S.xt[row][j4 + e] * S.sinv[j4 + e];
        }
    }
}

// ======================= host launcher =======================
extern "C" void kernel_launch(void* const* d_in, const int* in_sizes, int n_in,
                              void* d_out, int out_size)
{
    const float* corr    = (const float*)d_in[0];
    const float* src     = (const float*)d_in[1];
    const float* tgt     = (const float*)d_in[2];
    const float* iW      = (const float*)d_in[3];
    const float* ib      = (const float*)d_in[4];
    const float* pcnW    = (const float*)d_in[5];
    const float* pcnb    = (const float*)d_in[6];
    const float* pcng    = (const float*)d_in[7];
    const float* pcnbeta = (const float*)d_in[8];
    const float* qW  = (const float*)d_in[9];  const float* qb  = (const float*)d_in[10];
    const float* kW  = (const float*)d_in[11]; const float* kb  = (const float*)d_in[12];
    const float* vW  = (const float*)d_in[13]; const float* vb  = (const float*)d_in[14];
    const float* m1W = (const float*)d_in[15]; const float* m1b = (const float*)d_in[16];
    const float* m1g = (const float*)d_in[17]; const float* m1beta = (const float*)d_in[18];
    const float* m2W = (const float*)d_in[19]; const float* m2b = (const float*)d_in[20];
    const float* m2g = (const float*)d_in[21]; const float* m2beta = (const float*)d_in[22];
    const float* m3W = (const float*)d_in[23]; const float* m3b = (const float*)d_in[24];
    const float* c1W = (const float*)d_in[25]; const float* c1b = (const float*)d_in[26];
    const float* c2W = (const float*)d_in[27]; const float* c2b = (const float*)d_in[28];
    const float* c3W = (const float*)d_in[29]; const float* c3b = (const float*)d_in[30];
    float* out = (float*)d_out;

    float *x, *y, *v, *m, *h, *qt, *kt, *Op, *Lp, *Mm, *ps, *pq;
    float *scl, *shf, *scl1, *shf1, *scl2, *shf2;
    cudaGetSymbolAddress((void**)&x,  g_x);
    cudaGetSymbolAddress((void**)&y,  g_y);
    cudaGetSymbolAddress((void**)&v,  g_v);
    cudaGetSymbolAddress((void**)&m,  g_m);
    cudaGetSymbolAddress((void**)&h,  g_h);
    cudaGetSymbolAddress((void**)&qt, g_qt);
    cudaGetSymbolAddress((void**)&kt, g_kt);
    cudaGetSymbolAddress((void**)&Op, g_Op);
    cudaGetSymbolAddress((void**)&Lp, g_Lp);
    cudaGetSymbolAddress((void**)&Mm, g_Mm);
    cudaGetSymbolAddress((void**)&ps, g_ps);
    cudaGetSymbolAddress((void**)&pq, g_pq);
    cudaGetSymbolAddress((void**)&scl,  g_scl);  cudaGetSymbolAddress((void**)&shf,  g_shf);
    cudaGetSymbolAddress((void**)&scl1, g_scl1); cudaGetSymbolAddress((void**)&shf1, g_shf1);
    cudaGetSymbolAddress((void**)&scl2, g_scl2); cudaGetSymbolAddress((void**)&shf2, g_shf2);

    const int nT64  = (NPT + 63) / 64;    // 47 (flash / head)
    const int nT128 = (NPT + 127) / 128;  // 24 (convs)
    const int smemC128 = (int)sizeof(ConvS<128>);
    const int smemC64  = (int)sizeof(ConvS<64>);
    const int smemFlash = (int)sizeof(FlashS);
    const int smemHead  = (int)sizeof(HeadS);
    cudaFuncSetAttribute(conv_kernel<128,0,0,true>, cudaFuncAttributeMaxDynamicSharedMemorySize, smemC128);
    cudaFuncSetAttribute(conv_kernel<128,3,0,true>, cudaFuncAttributeMaxDynamicSharedMemorySize, smemC128);
    cudaFuncSetAttribute(conv_kernel<64,1,0,true>,  cudaFuncAttributeMaxDynamicSharedMemorySize, smemC64);
    cudaFuncSetAttribute(conv_kernel<64,1,2,false>, cudaFuncAttributeMaxDynamicSharedMemorySize, smemC64);
    cudaFuncSetAttribute(qkv_kernel, cudaFuncAttributeMaxDynamicSharedMemorySize, smemC128);
    cudaFuncSetAttribute(flash_kernel, cudaFuncAttributeMaxDynamicSharedMemorySize, smemFlash);
    cudaFuncSetAttribute(head_kernel,  cudaFuncAttributeMaxDynamicSharedMemorySize, smemHead);

    dim3 blk(256);
    init_conv_kernel<<<(BB*NPT + 127)/128, 128>>>(corr, iW, ib, x);

    for (int l = 0; l < LL; l++) {
        // PointCN conv (pre-BN output y) + stats partials
        conv_kernel<128,0,0,true><<<dim3(nT128,4,BB), blk, smemC128>>>(
            x, pcnW + (size_t)l*CCH*CCH, pcnb + l*CCH,
            nullptr, nullptr, nullptr, nullptr, nullptr,
            y, ps, pq, CCH);
        bnred_kernel<<<CCH, 32>>>(ps, pq, pcng + l*CCH, pcnbeta + l*CCH, scl, shf);

        // fused q/k/v (576 blocks; affine+relu on load; q,k transposed out)
        qkv_kernel<<<dim3(nT128,12,BB), blk, smemC128>>>(
            y, qW + (size_t)l*CCH*CCH, kW + (size_t)l*CCH*CCH, vW + (size_t)l*CCH*CCH,
            qb + l*CCH, kb + l*CCH, vb + l*CCH, scl, shf, qt, kt, v);

        // flash attention
        flash_kernel<<<dim3(nT64, ISPLIT, BB), 512, smemFlash>>>(qt, kt, v, src, tgt, Op, Lp, Mm);

        // m1: merge partials on load (weights from Mm/Lp), stats out
        conv_kernel<128,3,0,true><<<dim3(nT128,2,BB), blk, smemC128>>>(
            Op, m1W + (size_t)l*CH*CCH, m1b + l*CH,
            nullptr, nullptr, nullptr, Mm, Lp,
            m, ps, pq, CH);
        bnred_kernel<<<CH, 32>>>(ps, pq, m1g + l*CH, m1beta + l*CH, scl1, shf1);

        // m2: affine1 on load, stats out
        conv_kernel<64,1,0,true><<<dim3(nT128,2,BB), blk, smemC64>>>(
            m, m2W + (size_t)l*CH*CH, m2b + l*CH,
            scl1, shf1, nullptr, nullptr, nullptr,
            h, ps, pq, CH);
        bnred_kernel<<<CH, 32>>>(ps, pq, m2g + l*CH, m2beta + l*CH, scl2, shf2);

        // m3: affine2 on load, residual = relu(affine_pcn(y)), out -> x
        conv_kernel<64,1,2,false><<<dim3(nT128,4,BB), blk, smemC64>>>(
            h, m3W + (size_t)l*CCH*CH, m3b + l*CCH,
            scl2, shf2, y, scl, shf,
            x, nullptr, nullptr, CCH);
    }

    head_kernel<<<dim3(nT64, BB), 256, smemHead>>>(x, c1W, c1b, c2W, c2b, c3W, c3b, out);
}